// round 3
// baseline (speedup 1.0000x reference)
#include <cuda_runtime.h>
#include <cuda_bf16.h>

#define NN 50000
#define EE 800000
#define HDIM 64

// Scratch state (device globals: allocation-free)
__device__ float g_h[NN * HDIM];
__device__ float g_p[NN * HDIM];
__device__ float g_e[EE * HDIM];
__device__ float g_hagg[NN * HDIM];
__device__ float g_pagg[NN * HDIM];

struct Src {
    const float* base;
    int stride;  // row stride in floats
    int off;     // column offset in floats
    int mode;    // 0: index via send[], 1: index via rec[], 2: direct row
};

// Generic tiled gather-GEMM: out[row] (64 cols) = concat(chunks)(row) @ W + bias
// Each K-chunk is 64 wide (one concat segment). TILE 64 rows x 64 cols per CTA.
template <int NCHUNK>
__global__ void __launch_bounds__(256) gemm64_kernel(
    Src s0, Src s1, Src s2, Src s3, Src s4,
    const float* __restrict__ W, const float* __restrict__ bias,
    float* __restrict__ out, int atomic_out,
    const int* __restrict__ send, const int* __restrict__ rec, int nrows)
{
    __shared__ float XsT[64][68];  // [k][row]
    __shared__ float Ws[64][68];   // [k][col]
    __shared__ int s_send[64], s_rec[64];

    const int tid = threadIdx.x;
    const int row0 = blockIdx.x * 64;

    if (tid < 64) {
        int grow = row0 + tid;
        if (grow > nrows - 1) grow = nrows - 1;
        if (send) {
            s_send[tid] = send[grow];
            s_rec[tid] = rec[grow];
        } else {
            s_send[tid] = grow;
            s_rec[tid] = grow;
        }
    }
    __syncthreads();

    const int tx = tid & 15;       // col group
    const int ty = tid >> 4;       // row group
    float acc[4][4];
    {
        float4 bv = *(const float4*)(bias + tx * 4);
        #pragma unroll
        for (int i = 0; i < 4; i++) {
            acc[i][0] = bv.x; acc[i][1] = bv.y; acc[i][2] = bv.z; acc[i][3] = bv.w;
        }
    }

    // loader mapping: lr = row within tile (consecutive across a warp -> conflict-free STS),
    // lk = 16-wide k segment
    const int lr = tid & 63;
    const int lk = (tid >> 6) * 16;

    const Src srcs[5] = {s0, s1, s2, s3, s4};

    #pragma unroll
    for (int c = 0; c < NCHUNK; c++) {
        const Src s = srcs[c];
        int idx;
        if (s.mode == 0)      idx = s_send[lr];
        else if (s.mode == 1) idx = s_rec[lr];
        else {
            idx = row0 + lr;
            if (idx > nrows - 1) idx = nrows - 1;
        }
        const float* rp = s.base + (size_t)idx * s.stride + s.off + lk;
        #pragma unroll
        for (int i = 0; i < 4; i++) {
            float4 v = *(const float4*)(rp + 4 * i);
            XsT[lk + 4 * i + 0][lr] = v.x;
            XsT[lk + 4 * i + 1][lr] = v.y;
            XsT[lk + 4 * i + 2][lr] = v.z;
            XsT[lk + 4 * i + 3][lr] = v.w;
        }
        // weight chunk: rows c*64 .. c*64+63 of W, row-major [K][64]
        {
            const int wr = tid >> 2;
            const int wc = (tid & 3) * 16;
            const float* wp = W + (size_t)(c * 64 + wr) * 64 + wc;
            float4 w0 = ((const float4*)wp)[0];
            float4 w1 = ((const float4*)wp)[1];
            float4 w2 = ((const float4*)wp)[2];
            float4 w3 = ((const float4*)wp)[3];
            float* wd = &Ws[wr][wc];
            ((float4*)wd)[0] = w0; ((float4*)wd)[1] = w1;
            ((float4*)wd)[2] = w2; ((float4*)wd)[3] = w3;
        }
        __syncthreads();

        #pragma unroll 8
        for (int kk = 0; kk < 64; kk++) {
            float4 a = *(const float4*)&XsT[kk][ty * 4];
            float4 b = *(const float4*)&Ws[kk][tx * 4];
            acc[0][0] += a.x * b.x; acc[0][1] += a.x * b.y; acc[0][2] += a.x * b.z; acc[0][3] += a.x * b.w;
            acc[1][0] += a.y * b.x; acc[1][1] += a.y * b.y; acc[1][2] += a.y * b.z; acc[1][3] += a.y * b.w;
            acc[2][0] += a.z * b.x; acc[2][1] += a.z * b.y; acc[2][2] += a.z * b.z; acc[2][3] += a.z * b.w;
            acc[3][0] += a.w * b.x; acc[3][1] += a.w * b.y; acc[3][2] += a.w * b.z; acc[3][3] += a.w * b.w;
        }
        __syncthreads();
    }

    #pragma unroll
    for (int i = 0; i < 4; i++) {
        const int r = ty * 4 + i;
        const int grow = row0 + r;
        if (grow < nrows) {
            if (atomic_out) {
                float* op = out + (size_t)s_rec[r] * 64 + tx * 4;
                asm volatile("red.global.add.v4.f32 [%0], {%1, %2, %3, %4};"
                             :: "l"(op), "f"(acc[i][0]), "f"(acc[i][1]),
                                "f"(acc[i][2]), "f"(acc[i][3])
                             : "memory");
            } else {
                *(float4*)(out + (size_t)grow * 64 + tx * 4) =
                    make_float4(acc[i][0], acc[i][1], acc[i][2], acc[i][3]);
            }
        }
    }
}

// Small-K embedding: out[row] = x[row] (K) @ W[K][64] + b.  2 threads per row.
template <int K>
__global__ void __launch_bounds__(256) embed_smallK_kernel(
    const float* __restrict__ x, const float* __restrict__ W,
    const float* __restrict__ bias, float* __restrict__ out, int nrows)
{
    __shared__ float Ws[K][64];
    __shared__ float bs[64];
    const int tid = threadIdx.x;
    for (int i = tid; i < K * 64; i += 256) Ws[i / 64][i % 64] = W[i];
    if (tid < 64) bs[tid] = bias[tid];
    __syncthreads();

    const int row = blockIdx.x * 128 + (tid >> 1);
    const int half = (tid & 1) * 32;
    if (row >= nrows) return;

    float xv[K];
    const float4* xp = (const float4*)(x + (size_t)row * K);
    #pragma unroll
    for (int i = 0; i < K / 4; i++) {
        float4 v = xp[i];
        xv[4 * i + 0] = v.x; xv[4 * i + 1] = v.y;
        xv[4 * i + 2] = v.z; xv[4 * i + 3] = v.w;
    }

    float acc[32];
    #pragma unroll
    for (int j = 0; j < 32; j++) acc[j] = bs[half + j];
    #pragma unroll
    for (int k = 0; k < K; k++) {
        const float xk = xv[k];
        #pragma unroll
        for (int j = 0; j < 32; j++) acc[j] += xk * Ws[k][half + j];
    }
    float* op = out + (size_t)row * 64 + half;
    #pragma unroll
    for (int j = 0; j < 8; j++)
        ((float4*)op)[j] = make_float4(acc[4 * j], acc[4 * j + 1], acc[4 * j + 2], acc[4 * j + 3]);
}

extern "C" void kernel_launch(void* const* d_in, const int* in_sizes, int n_in,
                              void* d_out, int out_size)
{
    const float* h_in = (const float*)d_in[0];
    const float* e_in = (const float*)d_in[1];
    const float* p_in = (const float*)d_in[2];
    const int* ei = (const int*)d_in[3];
    const float* he_W = (const float*)d_in[4];
    const float* he_b = (const float*)d_in[5];
    const float* ee_W = (const float*)d_in[6];
    const float* ee_b = (const float*)d_in[7];
    const float* pe_W = (const float*)d_in[8];
    const float* pe_b = (const float*)d_in[9];
    const float* hm_W = (const float*)d_in[10];
    const float* hm_b = (const float*)d_in[11];
    const float* hu_W = (const float*)d_in[12];
    const float* hu_b = (const float*)d_in[13];
    const float* eu_W = (const float*)d_in[14];
    const float* eu_b = (const float*)d_in[15];
    const float* pm_W = (const float*)d_in[16];
    const float* pm_b = (const float*)d_in[17];
    const float* pu_W = (const float*)d_in[18];
    const float* pu_b = (const float*)d_in[19];

    const int* send = ei;
    const int* rec = ei + EE;

    float *h, *p, *e, *hagg, *pagg;
    cudaGetSymbolAddress((void**)&h, g_h);
    cudaGetSymbolAddress((void**)&p, g_p);
    cudaGetSymbolAddress((void**)&e, g_e);
    cudaGetSymbolAddress((void**)&hagg, g_hagg);
    cudaGetSymbolAddress((void**)&pagg, g_pagg);

    const int nodeGrid = (NN + 63) / 64;   // 782
    const int edgeGrid = EE / 64;          // 12500 (exact)

    const Src Z = {nullptr, 0, 0, 2};

    // Embeddings
    gemm64_kernel<2><<<nodeGrid, 256>>>(
        Src{h_in, 128, 0, 2}, Src{h_in, 128, 64, 2}, Z, Z, Z,
        he_W, he_b, h, 0, nullptr, nullptr, NN);
    embed_smallK_kernel<16><<<(EE + 127) / 128, 256>>>(e_in, ee_W, ee_b, e, EE);
    embed_smallK_kernel<16><<<(NN + 127) / 128, 256>>>(p_in, pe_W, pe_b, p, NN);

    for (int l = 0; l < 4; l++) {
        // h message + aggregate
        cudaMemsetAsync(hagg, 0, (size_t)NN * HDIM * sizeof(float), 0);
        gemm64_kernel<5><<<edgeGrid, 256>>>(
            Src{h, 64, 0, 0}, Src{p, 64, 0, 0}, Src{h, 64, 0, 1}, Src{p, 64, 0, 1}, Src{e, 64, 0, 2},
            hm_W + (size_t)l * 320 * 64, hm_b + l * 64, hagg, 1, send, rec, EE);
        // h update (in place)
        gemm64_kernel<2><<<nodeGrid, 256>>>(
            Src{h, 64, 0, 2}, Src{hagg, 64, 0, 2}, Z, Z, Z,
            hu_W + (size_t)l * 128 * 64, hu_b + l * 64, h, 0, nullptr, nullptr, NN);
        // e update (in place)
        gemm64_kernel<3><<<edgeGrid, 256>>>(
            Src{h, 64, 0, 0}, Src{h, 64, 0, 1}, Src{e, 64, 0, 2}, Z, Z,
            eu_W + (size_t)l * 192 * 64, eu_b + l * 64, e, 0, send, rec, EE);
        // p message + aggregate
        cudaMemsetAsync(pagg, 0, (size_t)NN * HDIM * sizeof(float), 0);
        gemm64_kernel<3><<<edgeGrid, 256>>>(
            Src{p, 64, 0, 0}, Src{p, 64, 0, 1}, Src{e, 64, 0, 2}, Z, Z,
            pm_W + (size_t)l * 192 * 64, pm_b + l * 64, pagg, 1, send, rec, EE);
        // p update (in place)
        gemm64_kernel<2><<<nodeGrid, 256>>>(
            Src{p, 64, 0, 2}, Src{pagg, 64, 0, 2}, Z, Z, Z,
            pu_W + (size_t)l * 128 * 64, pu_b + l * 64, p, 0, nullptr, nullptr, NN);
    }

    // Output: (h, p) concatenated
    cudaMemcpyAsync(d_out, h, (size_t)NN * HDIM * sizeof(float),
                    cudaMemcpyDeviceToDevice, 0);
    cudaMemcpyAsync((float*)d_out + (size_t)NN * HDIM, p,
                    (size_t)NN * HDIM * sizeof(float),
                    cudaMemcpyDeviceToDevice, 0);
}

// round 4
// speedup vs baseline: 1.2160x; 1.2160x over previous
#include <cuda_runtime.h>
#include <cuda_bf16.h>

#define NN 50000
#define EE 800000
#define HDIM 64

// Scratch state (device globals: allocation-free)
__device__ float g_h[NN * HDIM];
__device__ float g_p[NN * HDIM];
__device__ float g_e[EE * HDIM];
__device__ float g_hagg[NN * HDIM];
__device__ float g_pagg[NN * HDIM];

struct Src {
    const float* base;
    int stride;  // row stride in floats
    int off;     // column offset in floats
    int mode;    // 0: index via send[], 1: index via rec[], 2: direct row
};

// Generic tiled gather-GEMM: out[row] (64 cols) = concat(chunks)(row) @ W + bias
// Each K-chunk is 64 wide (one concat segment), staged in two 32-deep slabs.
// CTA tile: 256 rows x 64 cols, 256 threads, 8x8 register micro-tile.
template <int NCHUNK>
__global__ void __launch_bounds__(256, 2) gemm64_kernel(
    Src s0, Src s1, Src s2, Src s3, Src s4,
    const float* __restrict__ W, const float* __restrict__ bias,
    float* __restrict__ out, int atomic_out,
    const int* __restrict__ send, const int* __restrict__ rec, int nrows)
{
    __shared__ float XsT[32][264];  // [k][row] (256 rows + pad)
    __shared__ float Ws[32][72];    // [k][col] (64 cols + pad)
    __shared__ int s_send[256], s_rec[256];

    const int tid = threadIdx.x;
    const int row0 = blockIdx.x * 256;

    {
        int grow = row0 + tid;
        if (grow > nrows - 1) grow = nrows - 1;
        if (send) {
            s_send[tid] = send[grow];
            s_rec[tid] = rec[grow];
        } else {
            s_send[tid] = grow;
            s_rec[tid] = grow;
        }
    }
    __syncthreads();

    const int tx = tid & 7;        // col group: 8 cols
    const int ty = tid >> 3;       // row group: 8 rows (0..31)

    float acc[8][8];
    {
        float4 b0 = *(const float4*)(bias + tx * 8);
        float4 b1 = *(const float4*)(bias + tx * 8 + 4);
        #pragma unroll
        for (int i = 0; i < 8; i++) {
            acc[i][0] = b0.x; acc[i][1] = b0.y; acc[i][2] = b0.z; acc[i][3] = b0.w;
            acc[i][4] = b1.x; acc[i][5] = b1.y; acc[i][6] = b1.z; acc[i][7] = b1.w;
        }
    }

    const Src srcs[5] = {s0, s1, s2, s3, s4};

    // weight loader mapping (per stage): 32 rows x 64 cols, 8 floats/thread
    const int wr = tid >> 3;        // 0..31
    const int wc = (tid & 7) * 8;   // 0..56

    #pragma unroll
    for (int c = 0; c < NCHUNK; c++) {
        const Src s = srcs[c];
        int idx;
        if (s.mode == 0)      idx = s_send[tid];
        else if (s.mode == 1) idx = s_rec[tid];
        else {
            idx = row0 + tid;
            if (idx > nrows - 1) idx = nrows - 1;
        }
        const float* rp = s.base + (size_t)idx * s.stride + s.off;
        const float* wpb = W + (size_t)(c * 64) * 64;

        #pragma unroll
        for (int st = 0; st < 2; st++) {
            __syncthreads();  // previous compute done before overwriting smem

            // X slab: this thread owns row `tid`, loads 32 floats (k = st*32..)
            #pragma unroll
            for (int i = 0; i < 8; i++) {
                float4 v = *(const float4*)(rp + st * 32 + 4 * i);
                XsT[4 * i + 0][tid] = v.x;
                XsT[4 * i + 1][tid] = v.y;
                XsT[4 * i + 2][tid] = v.z;
                XsT[4 * i + 3][tid] = v.w;
            }
            // W slab: rows c*64 + st*32 + wr
            {
                const float* wp = wpb + (size_t)(st * 32 + wr) * 64 + wc;
                float4 w0 = ((const float4*)wp)[0];
                float4 w1 = ((const float4*)wp)[1];
                float* wd = &Ws[wr][wc];
                ((float4*)wd)[0] = w0;
                ((float4*)wd)[1] = w1;
            }
            __syncthreads();

            #pragma unroll 8
            for (int kk = 0; kk < 32; kk++) {
                float a[8], b[8];
                float4 a0 = *(const float4*)&XsT[kk][ty * 8];
                float4 a1 = *(const float4*)&XsT[kk][ty * 8 + 4];
                float4 bb0 = *(const float4*)&Ws[kk][tx * 8];
                float4 bb1 = *(const float4*)&Ws[kk][tx * 8 + 4];
                a[0] = a0.x; a[1] = a0.y; a[2] = a0.z; a[3] = a0.w;
                a[4] = a1.x; a[5] = a1.y; a[6] = a1.z; a[7] = a1.w;
                b[0] = bb0.x; b[1] = bb0.y; b[2] = bb0.z; b[3] = bb0.w;
                b[4] = bb1.x; b[5] = bb1.y; b[6] = bb1.z; b[7] = bb1.w;
                #pragma unroll
                for (int i = 0; i < 8; i++)
                    #pragma unroll
                    for (int j = 0; j < 8; j++)
                        acc[i][j] += a[i] * b[j];
            }
        }
    }

    #pragma unroll
    for (int i = 0; i < 8; i++) {
        const int r = ty * 8 + i;
        const int grow = row0 + r;
        if (grow < nrows) {
            if (atomic_out) {
                float* op = out + (size_t)s_rec[r] * 64 + tx * 8;
                asm volatile("red.global.add.v4.f32 [%0], {%1, %2, %3, %4};"
                             :: "l"(op), "f"(acc[i][0]), "f"(acc[i][1]),
                                "f"(acc[i][2]), "f"(acc[i][3])
                             : "memory");
                asm volatile("red.global.add.v4.f32 [%0], {%1, %2, %3, %4};"
                             :: "l"(op + 4), "f"(acc[i][4]), "f"(acc[i][5]),
                                "f"(acc[i][6]), "f"(acc[i][7])
                             : "memory");
            } else {
                float* op = out + (size_t)grow * 64 + tx * 8;
                *(float4*)op = make_float4(acc[i][0], acc[i][1], acc[i][2], acc[i][3]);
                *(float4*)(op + 4) = make_float4(acc[i][4], acc[i][5], acc[i][6], acc[i][7]);
            }
        }
    }
}

// Small-K embedding: out[row] = x[row] (K) @ W[K][64] + b.  2 threads per row.
template <int K>
__global__ void __launch_bounds__(256) embed_smallK_kernel(
    const float* __restrict__ x, const float* __restrict__ W,
    const float* __restrict__ bias, float* __restrict__ out, int nrows)
{
    __shared__ float Ws[K][64];
    __shared__ float bs[64];
    const int tid = threadIdx.x;
    for (int i = tid; i < K * 64; i += 256) Ws[i / 64][i % 64] = W[i];
    if (tid < 64) bs[tid] = bias[tid];
    __syncthreads();

    const int row = blockIdx.x * 128 + (tid >> 1);
    const int half = (tid & 1) * 32;
    if (row >= nrows) return;

    float xv[K];
    const float4* xp = (const float4*)(x + (size_t)row * K);
    #pragma unroll
    for (int i = 0; i < K / 4; i++) {
        float4 v = xp[i];
        xv[4 * i + 0] = v.x; xv[4 * i + 1] = v.y;
        xv[4 * i + 2] = v.z; xv[4 * i + 3] = v.w;
    }

    float acc[32];
    #pragma unroll
    for (int j = 0; j < 32; j++) acc[j] = bs[half + j];
    #pragma unroll
    for (int k = 0; k < K; k++) {
        const float xk = xv[k];
        #pragma unroll
        for (int j = 0; j < 32; j++) acc[j] += xk * Ws[k][half + j];
    }
    float* op = out + (size_t)row * 64 + half;
    #pragma unroll
    for (int j = 0; j < 8; j++)
        ((float4*)op)[j] = make_float4(acc[4 * j], acc[4 * j + 1], acc[4 * j + 2], acc[4 * j + 3]);
}

extern "C" void kernel_launch(void* const* d_in, const int* in_sizes, int n_in,
                              void* d_out, int out_size)
{
    const float* h_in = (const float*)d_in[0];
    const float* e_in = (const float*)d_in[1];
    const float* p_in = (const float*)d_in[2];
    const int* ei = (const int*)d_in[3];
    const float* he_W = (const float*)d_in[4];
    const float* he_b = (const float*)d_in[5];
    const float* ee_W = (const float*)d_in[6];
    const float* ee_b = (const float*)d_in[7];
    const float* pe_W = (const float*)d_in[8];
    const float* pe_b = (const float*)d_in[9];
    const float* hm_W = (const float*)d_in[10];
    const float* hm_b = (const float*)d_in[11];
    const float* hu_W = (const float*)d_in[12];
    const float* hu_b = (const float*)d_in[13];
    const float* eu_W = (const float*)d_in[14];
    const float* eu_b = (const float*)d_in[15];
    const float* pm_W = (const float*)d_in[16];
    const float* pm_b = (const float*)d_in[17];
    const float* pu_W = (const float*)d_in[18];
    const float* pu_b = (const float*)d_in[19];

    const int* send = ei;
    const int* rec = ei + EE;

    float *h, *p, *e, *hagg, *pagg;
    cudaGetSymbolAddress((void**)&h, g_h);
    cudaGetSymbolAddress((void**)&p, g_p);
    cudaGetSymbolAddress((void**)&e, g_e);
    cudaGetSymbolAddress((void**)&hagg, g_hagg);
    cudaGetSymbolAddress((void**)&pagg, g_pagg);

    const int nodeGrid = (NN + 255) / 256;   // 196
    const int edgeGrid = EE / 256;           // 3125 (exact)

    const Src Z = {nullptr, 0, 0, 2};

    // Embeddings
    gemm64_kernel<2><<<nodeGrid, 256>>>(
        Src{h_in, 128, 0, 2}, Src{h_in, 128, 64, 2}, Z, Z, Z,
        he_W, he_b, h, 0, nullptr, nullptr, NN);
    embed_smallK_kernel<16><<<(EE + 127) / 128, 256>>>(e_in, ee_W, ee_b, e, EE);
    embed_smallK_kernel<16><<<(NN + 127) / 128, 256>>>(p_in, pe_W, pe_b, p, NN);

    for (int l = 0; l < 4; l++) {
        // h message + aggregate
        cudaMemsetAsync(hagg, 0, (size_t)NN * HDIM * sizeof(float), 0);
        gemm64_kernel<5><<<edgeGrid, 256>>>(
            Src{h, 64, 0, 0}, Src{p, 64, 0, 0}, Src{h, 64, 0, 1}, Src{p, 64, 0, 1}, Src{e, 64, 0, 2},
            hm_W + (size_t)l * 320 * 64, hm_b + l * 64, hagg, 1, send, rec, EE);
        // h update (in place)
        gemm64_kernel<2><<<nodeGrid, 256>>>(
            Src{h, 64, 0, 2}, Src{hagg, 64, 0, 2}, Z, Z, Z,
            hu_W + (size_t)l * 128 * 64, hu_b + l * 64, h, 0, nullptr, nullptr, NN);
        // e update (in place)
        gemm64_kernel<3><<<edgeGrid, 256>>>(
            Src{h, 64, 0, 0}, Src{h, 64, 0, 1}, Src{e, 64, 0, 2}, Z, Z,
            eu_W + (size_t)l * 192 * 64, eu_b + l * 64, e, 0, send, rec, EE);
        // p message + aggregate
        cudaMemsetAsync(pagg, 0, (size_t)NN * HDIM * sizeof(float), 0);
        gemm64_kernel<3><<<edgeGrid, 256>>>(
            Src{p, 64, 0, 0}, Src{p, 64, 0, 1}, Src{e, 64, 0, 2}, Z, Z,
            pm_W + (size_t)l * 192 * 64, pm_b + l * 64, pagg, 1, send, rec, EE);
        // p update (in place)
        gemm64_kernel<2><<<nodeGrid, 256>>>(
            Src{p, 64, 0, 2}, Src{pagg, 64, 0, 2}, Z, Z, Z,
            pu_W + (size_t)l * 128 * 64, pu_b + l * 64, p, 0, nullptr, nullptr, NN);
    }

    // Output: (h, p) concatenated
    cudaMemcpyAsync(d_out, h, (size_t)NN * HDIM * sizeof(float),
                    cudaMemcpyDeviceToDevice, 0);
    cudaMemcpyAsync((float*)d_out + (size_t)NN * HDIM, p,
                    (size_t)NN * HDIM * sizeof(float),
                    cudaMemcpyDeviceToDevice, 0);
}

// round 5
// speedup vs baseline: 2.1449x; 1.7639x over previous
#include <cuda_runtime.h>
#include <cuda_bf16.h>
#include <cstdint>

#define NN 50000
#define EE 800000
#define HDIM 64

// Scratch state (device globals: allocation-free)
__device__ float g_h[NN * HDIM];
__device__ float g_p[NN * HDIM];
__device__ float g_e[EE * HDIM];
__device__ float g_hagg[NN * HDIM];
__device__ float g_pagg[NN * HDIM];

struct Src {
    const float* base;
    int stride;  // row stride in floats
    int off;     // column offset in floats
    int mode;    // 0: index via send[], 1: index via rec[], 2: direct row
};

__device__ __forceinline__ float to_tf32(float x) {
    uint32_t o;
    asm("cvt.rna.tf32.f32 %0, %1;" : "=r"(o) : "f"(x));
    return __uint_as_float(o);
}

// Generic tiled gather-GEMM using tf32 tensor cores.
// out[row] (64 cols) = concat(chunks)(row) @ W + bias
// Each K-chunk is 64 wide (one concat segment), staged in two 32-deep slabs.
// CTA: 256 rows x 64 cols, 256 threads (8 warps). Warp tile: 32 rows x 64 cols.
// mma.sync.m16n8k8 tf32, fp32 accumulate.
template <int NCHUNK>
__global__ void __launch_bounds__(256, 2) gemm64_kernel(
    Src s0, Src s1, Src s2, Src s3, Src s4,
    const float* __restrict__ W, const float* __restrict__ bias,
    float* __restrict__ out, int atomic_out,
    const int* __restrict__ send, const int* __restrict__ rec, int nrows)
{
    __shared__ float XsT[32][264];  // [k][row] (256 rows + 8 pad)
    __shared__ float Ws[32][72];    // [k][col] (64 cols + 8 pad)
    __shared__ int s_send[256], s_rec[256];
    __shared__ float bs[64];

    const int tid = threadIdx.x;
    const int row0 = blockIdx.x * 256;
    const int lane = tid & 31;
    const int warp = tid >> 5;
    const int warpRow0 = warp * 32;
    const int qrow = lane >> 2;  // 0..7
    const int qk = lane & 3;     // 0..3

    {
        int grow = row0 + tid;
        if (grow > nrows - 1) grow = nrows - 1;
        if (send) {
            s_send[tid] = send[grow];
            s_rec[tid] = rec[grow];
        } else {
            s_send[tid] = grow;
            s_rec[tid] = grow;
        }
        if (tid < 64) bs[tid] = bias[tid];
    }
    __syncthreads();

    // acc[mt][nt][0..3]: C fragments for m-tile mt (rows warpRow0+mt*16+{qrow,qrow+8}),
    // n-tile nt (cols nt*8 + 2*qk, +1)
    float acc[2][8][4];
    #pragma unroll
    for (int mt = 0; mt < 2; mt++)
        #pragma unroll
        for (int nt = 0; nt < 8; nt++)
            #pragma unroll
            for (int r = 0; r < 4; r++)
                acc[mt][nt][r] = 0.0f;

    const Src srcs[5] = {s0, s1, s2, s3, s4};

    // weight loader mapping (per stage): 32 rows x 64 cols, 8 floats/thread
    const int wr = tid >> 3;        // 0..31
    const int wc = (tid & 7) * 8;   // 0..56

    #pragma unroll
    for (int c = 0; c < NCHUNK; c++) {
        const Src s = srcs[c];
        int idx;
        if (s.mode == 0)      idx = s_send[tid];
        else if (s.mode == 1) idx = s_rec[tid];
        else {
            idx = row0 + tid;
            if (idx > nrows - 1) idx = nrows - 1;
        }
        const float* rp = s.base + (size_t)idx * s.stride + s.off;
        const float* wpb = W + (size_t)(c * 64) * 64;

        #pragma unroll
        for (int st = 0; st < 2; st++) {
            __syncthreads();  // previous compute done before overwriting smem

            // X slab: this thread owns row `tid`, loads 32 floats (k = st*32..)
            #pragma unroll
            for (int i = 0; i < 8; i++) {
                float4 v = *(const float4*)(rp + st * 32 + 4 * i);
                XsT[4 * i + 0][tid] = to_tf32(v.x);
                XsT[4 * i + 1][tid] = to_tf32(v.y);
                XsT[4 * i + 2][tid] = to_tf32(v.z);
                XsT[4 * i + 3][tid] = to_tf32(v.w);
            }
            // W slab: rows c*64 + st*32 + wr
            {
                const float* wp = wpb + (size_t)(st * 32 + wr) * 64 + wc;
                float4 w0 = ((const float4*)wp)[0];
                float4 w1 = ((const float4*)wp)[1];
                float* wd = &Ws[wr][wc];
                wd[0] = to_tf32(w0.x); wd[1] = to_tf32(w0.y);
                wd[2] = to_tf32(w0.z); wd[3] = to_tf32(w0.w);
                wd[4] = to_tf32(w1.x); wd[5] = to_tf32(w1.y);
                wd[6] = to_tf32(w1.z); wd[7] = to_tf32(w1.w);
            }
            __syncthreads();

            // 4 k8-steps over this 32-deep slab
            #pragma unroll
            for (int ks = 0; ks < 4; ks++) {
                const int k0 = ks * 8;
                uint32_t a[2][4], b[8][2];
                #pragma unroll
                for (int mt = 0; mt < 2; mt++) {
                    const int r = warpRow0 + mt * 16 + qrow;
                    a[mt][0] = __float_as_uint(XsT[k0 + qk][r]);
                    a[mt][1] = __float_as_uint(XsT[k0 + qk][r + 8]);
                    a[mt][2] = __float_as_uint(XsT[k0 + qk + 4][r]);
                    a[mt][3] = __float_as_uint(XsT[k0 + qk + 4][r + 8]);
                }
                #pragma unroll
                for (int nt = 0; nt < 8; nt++) {
                    b[nt][0] = __float_as_uint(Ws[k0 + qk][nt * 8 + qrow]);
                    b[nt][1] = __float_as_uint(Ws[k0 + qk + 4][nt * 8 + qrow]);
                }
                #pragma unroll
                for (int mt = 0; mt < 2; mt++)
                    #pragma unroll
                    for (int nt = 0; nt < 8; nt++) {
                        asm volatile(
                            "mma.sync.aligned.m16n8k8.row.col.f32.tf32.tf32.f32 "
                            "{%0,%1,%2,%3}, {%4,%5,%6,%7}, {%8,%9}, {%0,%1,%2,%3};"
                            : "+f"(acc[mt][nt][0]), "+f"(acc[mt][nt][1]),
                              "+f"(acc[mt][nt][2]), "+f"(acc[mt][nt][3])
                            : "r"(a[mt][0]), "r"(a[mt][1]), "r"(a[mt][2]), "r"(a[mt][3]),
                              "r"(b[nt][0]), "r"(b[nt][1]));
                    }
            }
        }
    }

    // Epilogue: add bias, write/reduce.
    #pragma unroll
    for (int mt = 0; mt < 2; mt++) {
        #pragma unroll
        for (int half = 0; half < 2; half++) {
            const int r = warpRow0 + mt * 16 + qrow + half * 8;
            const int grow = row0 + r;
            if (grow < nrows) {
                #pragma unroll
                for (int nt = 0; nt < 8; nt++) {
                    const int col = nt * 8 + 2 * qk;
                    float v0 = acc[mt][nt][half * 2 + 0] + bs[col];
                    float v1 = acc[mt][nt][half * 2 + 1] + bs[col + 1];
                    if (atomic_out) {
                        float* op = out + (size_t)s_rec[r] * 64 + col;
                        asm volatile("red.global.add.v2.f32 [%0], {%1, %2};"
                                     :: "l"(op), "f"(v0), "f"(v1) : "memory");
                    } else {
                        *(float2*)(out + (size_t)grow * 64 + col) = make_float2(v0, v1);
                    }
                }
            }
        }
    }
}

// Small-K embedding: out[row] = x[row] (K) @ W[K][64] + b.  2 threads per row. fp32.
template <int K>
__global__ void __launch_bounds__(256) embed_smallK_kernel(
    const float* __restrict__ x, const float* __restrict__ W,
    const float* __restrict__ bias, float* __restrict__ out, int nrows)
{
    __shared__ float Ws[K][64];
    __shared__ float bs[64];
    const int tid = threadIdx.x;
    for (int i = tid; i < K * 64; i += 256) Ws[i / 64][i % 64] = W[i];
    if (tid < 64) bs[tid] = bias[tid];
    __syncthreads();

    const int row = blockIdx.x * 128 + (tid >> 1);
    const int half = (tid & 1) * 32;
    if (row >= nrows) return;

    float xv[K];
    const float4* xp = (const float4*)(x + (size_t)row * K);
    #pragma unroll
    for (int i = 0; i < K / 4; i++) {
        float4 v = xp[i];
        xv[4 * i + 0] = v.x; xv[4 * i + 1] = v.y;
        xv[4 * i + 2] = v.z; xv[4 * i + 3] = v.w;
    }

    float acc[32];
    #pragma unroll
    for (int j = 0; j < 32; j++) acc[j] = bs[half + j];
    #pragma unroll
    for (int k = 0; k < K; k++) {
        const float xk = xv[k];
        #pragma unroll
        for (int j = 0; j < 32; j++) acc[j] += xk * Ws[k][half + j];
    }
    float* op = out + (size_t)row * 64 + half;
    #pragma unroll
    for (int j = 0; j < 8; j++)
        ((float4*)op)[j] = make_float4(acc[4 * j], acc[4 * j + 1], acc[4 * j + 2], acc[4 * j + 3]);
}

extern "C" void kernel_launch(void* const* d_in, const int* in_sizes, int n_in,
                              void* d_out, int out_size)
{
    const float* h_in = (const float*)d_in[0];
    const float* e_in = (const float*)d_in[1];
    const float* p_in = (const float*)d_in[2];
    const int* ei = (const int*)d_in[3];
    const float* he_W = (const float*)d_in[4];
    const float* he_b = (const float*)d_in[5];
    const float* ee_W = (const float*)d_in[6];
    const float* ee_b = (const float*)d_in[7];
    const float* pe_W = (const float*)d_in[8];
    const float* pe_b = (const float*)d_in[9];
    const float* hm_W = (const float*)d_in[10];
    const float* hm_b = (const float*)d_in[11];
    const float* hu_W = (const float*)d_in[12];
    const float* hu_b = (const float*)d_in[13];
    const float* eu_W = (const float*)d_in[14];
    const float* eu_b = (const float*)d_in[15];
    const float* pm_W = (const float*)d_in[16];
    const float* pm_b = (const float*)d_in[17];
    const float* pu_W = (const float*)d_in[18];
    const float* pu_b = (const float*)d_in[19];

    const int* send = ei;
    const int* rec = ei + EE;

    float *h, *p, *e, *hagg, *pagg;
    cudaGetSymbolAddress((void**)&h, g_h);
    cudaGetSymbolAddress((void**)&p, g_p);
    cudaGetSymbolAddress((void**)&e, g_e);
    cudaGetSymbolAddress((void**)&hagg, g_hagg);
    cudaGetSymbolAddress((void**)&pagg, g_pagg);

    const int nodeGrid = (NN + 255) / 256;   // 196
    const int edgeGrid = EE / 256;           // 3125 (exact)

    const Src Z = {nullptr, 0, 0, 2};

    // Embeddings
    gemm64_kernel<2><<<nodeGrid, 256>>>(
        Src{h_in, 128, 0, 2}, Src{h_in, 128, 64, 2}, Z, Z, Z,
        he_W, he_b, h, 0, nullptr, nullptr, NN);
    embed_smallK_kernel<16><<<(EE + 127) / 128, 256>>>(e_in, ee_W, ee_b, e, EE);
    embed_smallK_kernel<16><<<(NN + 127) / 128, 256>>>(p_in, pe_W, pe_b, p, NN);

    for (int l = 0; l < 4; l++) {
        // h message + aggregate
        cudaMemsetAsync(hagg, 0, (size_t)NN * HDIM * sizeof(float), 0);
        gemm64_kernel<5><<<edgeGrid, 256>>>(
            Src{h, 64, 0, 0}, Src{p, 64, 0, 0}, Src{h, 64, 0, 1}, Src{p, 64, 0, 1}, Src{e, 64, 0, 2},
            hm_W + (size_t)l * 320 * 64, hm_b + l * 64, hagg, 1, send, rec, EE);
        // h update (in place)
        gemm64_kernel<2><<<nodeGrid, 256>>>(
            Src{h, 64, 0, 2}, Src{hagg, 64, 0, 2}, Z, Z, Z,
            hu_W + (size_t)l * 128 * 64, hu_b + l * 64, h, 0, nullptr, nullptr, NN);
        // e update (in place)
        gemm64_kernel<3><<<edgeGrid, 256>>>(
            Src{h, 64, 0, 0}, Src{h, 64, 0, 1}, Src{e, 64, 0, 2}, Z, Z,
            eu_W + (size_t)l * 192 * 64, eu_b + l * 64, e, 0, send, rec, EE);
        // p message + aggregate
        cudaMemsetAsync(pagg, 0, (size_t)NN * HDIM * sizeof(float), 0);
        gemm64_kernel<3><<<edgeGrid, 256>>>(
            Src{p, 64, 0, 0}, Src{p, 64, 0, 1}, Src{e, 64, 0, 2}, Z, Z,
            pm_W + (size_t)l * 192 * 64, pm_b + l * 64, pagg, 1, send, rec, EE);
        // p update (in place)
        gemm64_kernel<2><<<nodeGrid, 256>>>(
            Src{p, 64, 0, 2}, Src{pagg, 64, 0, 2}, Z, Z, Z,
            pu_W + (size_t)l * 128 * 64, pu_b + l * 64, p, 0, nullptr, nullptr, NN);
    }

    // Output: (h, p) concatenated
    cudaMemcpyAsync(d_out, h, (size_t)NN * HDIM * sizeof(float),
                    cudaMemcpyDeviceToDevice, 0);
    cudaMemcpyAsync((float*)d_out + (size_t)NN * HDIM, p,
                    (size_t)NN * HDIM * sizeof(float),
                    cudaMemcpyDeviceToDevice, 0);
}

// round 6
// speedup vs baseline: 2.7439x; 1.2793x over previous
#include <cuda_runtime.h>
#include <cuda_bf16.h>
#include <cstdint>

#define NN 50000
#define EE 800000

// Scratch state (device globals: allocation-free)
__device__ float g_h[NN * 64];
__device__ float g_p[NN * 64];
__device__ float g_e[EE * 64];
__device__ float g_hagg[NN * 64];
__device__ float g_pagg[NN * 64];
__device__ float g_nA[NN * 64];
__device__ float g_nB[NN * 64];
__device__ int   g_deg[NN];
__device__ float g_zero64[64];   // stays zero (never written)

struct Src {
    const float* base;
    int stride;
    int off;
    int mode;  // 2: direct row (only mode used now)
};

// ---------------------------------------------------------------------------
// fp32 node-level GEMM (validated R4 kernel). out[row](64) = concat(chunks)@W + b
// CTA 256 rows x 64 cols, 8x8 register micro-tile.
template <int NCHUNK>
__global__ void __launch_bounds__(256, 2) gemm64_kernel(
    Src s0, Src s1,
    const float* __restrict__ W, const float* __restrict__ bias,
    float* __restrict__ out, int nrows)
{
    __shared__ float XsT[32][264];
    __shared__ float Ws[32][72];

    const int tid = threadIdx.x;
    const int row0 = blockIdx.x * 256;

    const int tx = tid & 7;
    const int ty = tid >> 3;

    float acc[8][8];
    {
        float4 b0 = *(const float4*)(bias + tx * 8);
        float4 b1 = *(const float4*)(bias + tx * 8 + 4);
        #pragma unroll
        for (int i = 0; i < 8; i++) {
            acc[i][0] = b0.x; acc[i][1] = b0.y; acc[i][2] = b0.z; acc[i][3] = b0.w;
            acc[i][4] = b1.x; acc[i][5] = b1.y; acc[i][6] = b1.z; acc[i][7] = b1.w;
        }
    }

    const Src srcs[2] = {s0, s1};
    const int wr = tid >> 3;
    const int wc = (tid & 7) * 8;

    int myrow = row0 + tid;
    if (myrow > nrows - 1) myrow = nrows - 1;

    #pragma unroll
    for (int c = 0; c < NCHUNK; c++) {
        const Src s = srcs[c];
        const float* rp = s.base + (size_t)myrow * s.stride + s.off;
        const float* wpb = W + (size_t)(c * 64) * 64;

        #pragma unroll
        for (int st = 0; st < 2; st++) {
            __syncthreads();
            #pragma unroll
            for (int i = 0; i < 8; i++) {
                float4 v = *(const float4*)(rp + st * 32 + 4 * i);
                XsT[4 * i + 0][tid] = v.x;
                XsT[4 * i + 1][tid] = v.y;
                XsT[4 * i + 2][tid] = v.z;
                XsT[4 * i + 3][tid] = v.w;
            }
            {
                const float* wp = wpb + (size_t)(st * 32 + wr) * 64 + wc;
                float4 w0 = ((const float4*)wp)[0];
                float4 w1 = ((const float4*)wp)[1];
                float* wd = &Ws[wr][wc];
                ((float4*)wd)[0] = w0;
                ((float4*)wd)[1] = w1;
            }
            __syncthreads();

            #pragma unroll 8
            for (int kk = 0; kk < 32; kk++) {
                float a[8], b[8];
                float4 a0 = *(const float4*)&XsT[kk][ty * 8];
                float4 a1 = *(const float4*)&XsT[kk][ty * 8 + 4];
                float4 bb0 = *(const float4*)&Ws[kk][tx * 8];
                float4 bb1 = *(const float4*)&Ws[kk][tx * 8 + 4];
                a[0] = a0.x; a[1] = a0.y; a[2] = a0.z; a[3] = a0.w;
                a[4] = a1.x; a[5] = a1.y; a[6] = a1.z; a[7] = a1.w;
                b[0] = bb0.x; b[1] = bb0.y; b[2] = bb0.z; b[3] = bb0.w;
                b[4] = bb1.x; b[5] = bb1.y; b[6] = bb1.z; b[7] = bb1.w;
                #pragma unroll
                for (int i = 0; i < 8; i++)
                    #pragma unroll
                    for (int j = 0; j < 8; j++)
                        acc[i][j] += a[i] * b[j];
            }
        }
    }

    #pragma unroll
    for (int i = 0; i < 8; i++) {
        const int grow = row0 + ty * 8 + i;
        if (grow < nrows) {
            float* op = out + (size_t)grow * 64 + tx * 8;
            *(float4*)op = make_float4(acc[i][0], acc[i][1], acc[i][2], acc[i][3]);
            *(float4*)(op + 4) = make_float4(acc[i][4], acc[i][5], acc[i][6], acc[i][7]);
        }
    }
}

// ---------------------------------------------------------------------------
// Streaming edge GEMM, 3xTF32 (fp32-accurate): acc = e_tile @ W3.
// MODE 0: red.add  out[rec[r]] += acc + gA[send[r]]            (bias folded in init_agg)
// MODE 1: out[r] = acc + gA[send[r]] + gB[rec[r]] + bias       (e update, in place)
template <int MODE>
__global__ void __launch_bounds__(256, 2) streamE_kernel(
    const float* __restrict__ X, const float* __restrict__ W,
    const float* __restrict__ bias, const float* __restrict__ gA,
    const float* __restrict__ gB, const int* __restrict__ send,
    const int* __restrict__ rec, float* __restrict__ out)
{
    extern __shared__ float dyn[];
    float* Xhi = dyn;                 // [256][36]
    float* Xlo = Xhi + 256 * 36;
    float* Whi = Xlo + 256 * 36;      // [32][72]
    float* Wlo = Whi + 32 * 72;
    __shared__ int s_send[256], s_rec[256];
    __shared__ float bs[64];

    const int tid = threadIdx.x;
    const int row0 = blockIdx.x * 256;
    const int lane = tid & 31;
    const int warp = tid >> 5;
    const int warpRow0 = warp * 32;
    const int qrow = lane >> 2;
    const int qk = lane & 3;

    s_send[tid] = send[row0 + tid];
    s_rec[tid] = rec[row0 + tid];
    if (tid < 64) bs[tid] = bias[tid];

    float acc[2][8][4];
    #pragma unroll
    for (int mt = 0; mt < 2; mt++)
        #pragma unroll
        for (int nt = 0; nt < 8; nt++)
            #pragma unroll
            for (int r = 0; r < 4; r++) acc[mt][nt][r] = 0.0f;

    const float* base = X + (size_t)row0 * 64;
    const int wr = tid >> 3;
    const int wc = (tid & 7) * 8;

    #pragma unroll
    for (int st = 0; st < 2; st++) {
        __syncthreads();
        // X slab: coalesced — warp covers 4 full rows per LDG.128
        #pragma unroll
        for (int i = 0; i < 8; i++) {
            const int g = tid + 256 * i;
            const int row = g >> 3;
            const int f = (g & 7) * 4;
            float4 v = *(const float4*)(base + (size_t)row * 64 + st * 32 + f);
            float xs[4] = {v.x, v.y, v.z, v.w};
            float hi[4], lo[4];
            #pragma unroll
            for (int j = 0; j < 4; j++) {
                uint32_t hb;
                asm("cvt.rna.tf32.f32 %0, %1;" : "=r"(hb) : "f"(xs[j]));
                hi[j] = __uint_as_float(hb);
                float l = xs[j] - hi[j];
                uint32_t lb;
                asm("cvt.rna.tf32.f32 %0, %1;" : "=r"(lb) : "f"(l));
                lo[j] = __uint_as_float(lb);
            }
            *(float4*)&Xhi[row * 36 + f] = make_float4(hi[0], hi[1], hi[2], hi[3]);
            *(float4*)&Xlo[row * 36 + f] = make_float4(lo[0], lo[1], lo[2], lo[3]);
        }
        // W slab
        {
            const float* wp = W + (size_t)(st * 32 + wr) * 64 + wc;
            #pragma unroll
            for (int j = 0; j < 8; j++) {
                float w = wp[j];
                uint32_t hb;
                asm("cvt.rna.tf32.f32 %0, %1;" : "=r"(hb) : "f"(w));
                float hf = __uint_as_float(hb);
                float l = w - hf;
                uint32_t lb;
                asm("cvt.rna.tf32.f32 %0, %1;" : "=r"(lb) : "f"(l));
                Whi[wr * 72 + wc + j] = hf;
                Wlo[wr * 72 + wc + j] = __uint_as_float(lb);
            }
        }
        __syncthreads();

        #pragma unroll
        for (int ks = 0; ks < 4; ks++) {
            const int k0 = ks * 8;
            uint32_t ah[2][4], al[2][4];
            #pragma unroll
            for (int mt = 0; mt < 2; mt++) {
                const int r = warpRow0 + mt * 16 + qrow;
                ah[mt][0] = __float_as_uint(Xhi[r * 36 + k0 + qk]);
                ah[mt][1] = __float_as_uint(Xhi[(r + 8) * 36 + k0 + qk]);
                ah[mt][2] = __float_as_uint(Xhi[r * 36 + k0 + qk + 4]);
                ah[mt][3] = __float_as_uint(Xhi[(r + 8) * 36 + k0 + qk + 4]);
                al[mt][0] = __float_as_uint(Xlo[r * 36 + k0 + qk]);
                al[mt][1] = __float_as_uint(Xlo[(r + 8) * 36 + k0 + qk]);
                al[mt][2] = __float_as_uint(Xlo[r * 36 + k0 + qk + 4]);
                al[mt][3] = __float_as_uint(Xlo[(r + 8) * 36 + k0 + qk + 4]);
            }
            #pragma unroll
            for (int nt = 0; nt < 8; nt++) {
                const int cb = nt * 8 + qrow;
                uint32_t bh0 = __float_as_uint(Whi[(k0 + qk) * 72 + cb]);
                uint32_t bh1 = __float_as_uint(Whi[(k0 + qk + 4) * 72 + cb]);
                uint32_t bl0 = __float_as_uint(Wlo[(k0 + qk) * 72 + cb]);
                uint32_t bl1 = __float_as_uint(Wlo[(k0 + qk + 4) * 72 + cb]);
                #pragma unroll
                for (int mt = 0; mt < 2; mt++) {
                    asm volatile(
                        "mma.sync.aligned.m16n8k8.row.col.f32.tf32.tf32.f32 "
                        "{%0,%1,%2,%3}, {%4,%5,%6,%7}, {%8,%9}, {%0,%1,%2,%3};"
                        : "+f"(acc[mt][nt][0]), "+f"(acc[mt][nt][1]),
                          "+f"(acc[mt][nt][2]), "+f"(acc[mt][nt][3])
                        : "r"(ah[mt][0]), "r"(ah[mt][1]), "r"(ah[mt][2]), "r"(ah[mt][3]),
                          "r"(bh0), "r"(bh1));
                    asm volatile(
                        "mma.sync.aligned.m16n8k8.row.col.f32.tf32.tf32.f32 "
                        "{%0,%1,%2,%3}, {%4,%5,%6,%7}, {%8,%9}, {%0,%1,%2,%3};"
                        : "+f"(acc[mt][nt][0]), "+f"(acc[mt][nt][1]),
                          "+f"(acc[mt][nt][2]), "+f"(acc[mt][nt][3])
                        : "r"(ah[mt][0]), "r"(ah[mt][1]), "r"(ah[mt][2]), "r"(ah[mt][3]),
                          "r"(bl0), "r"(bl1));
                    asm volatile(
                        "mma.sync.aligned.m16n8k8.row.col.f32.tf32.tf32.f32 "
                        "{%0,%1,%2,%3}, {%4,%5,%6,%7}, {%8,%9}, {%0,%1,%2,%3};"
                        : "+f"(acc[mt][nt][0]), "+f"(acc[mt][nt][1]),
                          "+f"(acc[mt][nt][2]), "+f"(acc[mt][nt][3])
                        : "r"(al[mt][0]), "r"(al[mt][1]), "r"(al[mt][2]), "r"(al[mt][3]),
                          "r"(bh0), "r"(bh1));
                }
            }
        }
    }

    #pragma unroll
    for (int mt = 0; mt < 2; mt++) {
        #pragma unroll
        for (int half = 0; half < 2; half++) {
            const int r = warpRow0 + mt * 16 + qrow + half * 8;
            if (MODE == 0) {
                const float* ga = gA + (size_t)s_send[r] * 64;
                float* op = out + (size_t)s_rec[r] * 64;
                #pragma unroll
                for (int nt = 0; nt < 8; nt++) {
                    const int col = nt * 8 + 2 * qk;
                    float2 a2 = __ldg((const float2*)(ga + col));
                    float v0 = acc[mt][nt][half * 2 + 0] + a2.x;
                    float v1 = acc[mt][nt][half * 2 + 1] + a2.y;
                    asm volatile("red.global.add.v2.f32 [%0], {%1, %2};"
                                 :: "l"(op + col), "f"(v0), "f"(v1) : "memory");
                }
            } else {
                const float* ga = gA + (size_t)s_send[r] * 64;
                const float* gb = gB + (size_t)s_rec[r] * 64;
                float* op = out + (size_t)(row0 + r) * 64;
                #pragma unroll
                for (int nt = 0; nt < 8; nt++) {
                    const int col = nt * 8 + 2 * qk;
                    float2 a2 = __ldg((const float2*)(ga + col));
                    float2 b2 = __ldg((const float2*)(gb + col));
                    float v0 = acc[mt][nt][half * 2 + 0] + a2.x + b2.x + bs[col];
                    float v1 = acc[mt][nt][half * 2 + 1] + a2.y + b2.y + bs[col + 1];
                    *(float2*)(op + col) = make_float2(v0, v1);
                }
            }
        }
    }
}

// ---------------------------------------------------------------------------
__global__ void __launch_bounds__(256) deg_kernel(const int* __restrict__ rec,
                                                  int* __restrict__ deg)
{
    int i = blockIdx.x * 256 + threadIdx.x;
    if (i < EE) atomicAdd(&deg[rec[i]], 1);
}

// agg[r][c] = deg[r] * (nodeB[r][c] + bias[c])
__global__ void __launch_bounds__(256) init_agg_kernel(
    const float* __restrict__ nodeB, const float* __restrict__ bias,
    const int* __restrict__ deg, float* __restrict__ agg)
{
    int i = blockIdx.x * 256 + threadIdx.x;
    if (i < NN * 64) {
        int r = i >> 6, c = i & 63;
        agg[i] = (float)deg[r] * (nodeB[i] + bias[c]);
    }
}

// Small-K embedding (fp32)
template <int K>
__global__ void __launch_bounds__(256) embed_smallK_kernel(
    const float* __restrict__ x, const float* __restrict__ W,
    const float* __restrict__ bias, float* __restrict__ out, int nrows)
{
    __shared__ float Ws[K][64];
    __shared__ float bsm[64];
    const int tid = threadIdx.x;
    for (int i = tid; i < K * 64; i += 256) Ws[i / 64][i % 64] = W[i];
    if (tid < 64) bsm[tid] = bias[tid];
    __syncthreads();

    const int row = blockIdx.x * 128 + (tid >> 1);
    const int half = (tid & 1) * 32;
    if (row >= nrows) return;

    float xv[K];
    const float4* xp = (const float4*)(x + (size_t)row * K);
    #pragma unroll
    for (int i = 0; i < K / 4; i++) {
        float4 v = xp[i];
        xv[4 * i + 0] = v.x; xv[4 * i + 1] = v.y;
        xv[4 * i + 2] = v.z; xv[4 * i + 3] = v.w;
    }

    float acc[32];
    #pragma unroll
    for (int j = 0; j < 32; j++) acc[j] = bsm[half + j];
    #pragma unroll
    for (int k = 0; k < K; k++) {
        const float xk = xv[k];
        #pragma unroll
        for (int j = 0; j < 32; j++) acc[j] += xk * Ws[k][half + j];
    }
    float* op = out + (size_t)row * 64 + half;
    #pragma unroll
    for (int j = 0; j < 8; j++)
        ((float4*)op)[j] = make_float4(acc[4 * j], acc[4 * j + 1], acc[4 * j + 2], acc[4 * j + 3]);
}

// ---------------------------------------------------------------------------
extern "C" void kernel_launch(void* const* d_in, const int* in_sizes, int n_in,
                              void* d_out, int out_size)
{
    const float* h_in = (const float*)d_in[0];
    const float* e_in = (const float*)d_in[1];
    const float* p_in = (const float*)d_in[2];
    const int* ei = (const int*)d_in[3];
    const float* he_W = (const float*)d_in[4];
    const float* he_b = (const float*)d_in[5];
    const float* ee_W = (const float*)d_in[6];
    const float* ee_b = (const float*)d_in[7];
    const float* pe_W = (const float*)d_in[8];
    const float* pe_b = (const float*)d_in[9];
    const float* hm_W = (const float*)d_in[10];
    const float* hm_b = (const float*)d_in[11];
    const float* hu_W = (const float*)d_in[12];
    const float* hu_b = (const float*)d_in[13];
    const float* eu_W = (const float*)d_in[14];
    const float* eu_b = (const float*)d_in[15];
    const float* pm_W = (const float*)d_in[16];
    const float* pm_b = (const float*)d_in[17];
    const float* pu_W = (const float*)d_in[18];
    const float* pu_b = (const float*)d_in[19];

    const int* send = ei;
    const int* rec = ei + EE;

    float *h, *p, *e, *hagg, *pagg, *nA, *nB, *zero64;
    int* deg;
    cudaGetSymbolAddress((void**)&h, g_h);
    cudaGetSymbolAddress((void**)&p, g_p);
    cudaGetSymbolAddress((void**)&e, g_e);
    cudaGetSymbolAddress((void**)&hagg, g_hagg);
    cudaGetSymbolAddress((void**)&pagg, g_pagg);
    cudaGetSymbolAddress((void**)&nA, g_nA);
    cudaGetSymbolAddress((void**)&nB, g_nB);
    cudaGetSymbolAddress((void**)&deg, g_deg);
    cudaGetSymbolAddress((void**)&zero64, g_zero64);

    const int SME_DYN = (256 * 36 * 2 + 32 * 72 * 2) * 4;  // 92160 B
    cudaFuncSetAttribute(streamE_kernel<0>, cudaFuncAttributeMaxDynamicSharedMemorySize, SME_DYN);
    cudaFuncSetAttribute(streamE_kernel<1>, cudaFuncAttributeMaxDynamicSharedMemorySize, SME_DYN);

    const int nodeGrid = (NN + 255) / 256;   // 196
    const int edgeGrid = EE / 256;           // 3125
    const int aggGrid = (NN * 64 + 255) / 256;

    const Src Z = {nullptr, 0, 0, 2};

    // Embeddings
    gemm64_kernel<2><<<nodeGrid, 256>>>(
        Src{h_in, 128, 0, 2}, Src{h_in, 128, 64, 2}, he_W, he_b, h, NN);
    embed_smallK_kernel<16><<<(EE + 127) / 128, 256>>>(e_in, ee_W, ee_b, e, EE);
    embed_smallK_kernel<16><<<(NN + 127) / 128, 256>>>(p_in, pe_W, pe_b, p, NN);

    // Degree (once)
    cudaMemsetAsync(deg, 0, NN * sizeof(int), 0);
    deg_kernel<<<edgeGrid, 256>>>(rec, deg);

    for (int l = 0; l < 4; l++) {
        const float* hmW = hm_W + (size_t)l * 320 * 64;
        const float* huW = hu_W + (size_t)l * 128 * 64;
        const float* euW = eu_W + (size_t)l * 192 * 64;
        const float* pmW = pm_W + (size_t)l * 192 * 64;
        const float* puW = pu_W + (size_t)l * 128 * 64;

        // ---- h message: nodeA=[h,p]@W[0:128), nodeB=[h,p]@W[128:256), e@W[256:320)
        gemm64_kernel<2><<<nodeGrid, 256>>>(
            Src{h, 64, 0, 2}, Src{p, 64, 0, 2}, hmW, zero64, nA, NN);
        gemm64_kernel<2><<<nodeGrid, 256>>>(
            Src{h, 64, 0, 2}, Src{p, 64, 0, 2}, hmW + 128 * 64, zero64, nB, NN);
        init_agg_kernel<<<aggGrid, 256>>>(nB, hm_b + l * 64, deg, hagg);
        streamE_kernel<0><<<edgeGrid, 256, SME_DYN>>>(
            e, hmW + 256 * 64, hm_b + l * 64, nA, nullptr, send, rec, hagg);
        // ---- h update
        gemm64_kernel<2><<<nodeGrid, 256>>>(
            Src{h, 64, 0, 2}, Src{hagg, 64, 0, 2}, huW, hu_b + l * 64, h, NN);
        // ---- e update: eA=h@W[0:64), eB=h@W[64:128), e@W[128:192) + gathers
        gemm64_kernel<1><<<nodeGrid, 256>>>(
            Src{h, 64, 0, 2}, Z, euW, zero64, nA, NN);
        gemm64_kernel<1><<<nodeGrid, 256>>>(
            Src{h, 64, 0, 2}, Z, euW + 64 * 64, zero64, nB, NN);
        streamE_kernel<1><<<edgeGrid, 256, SME_DYN>>>(
            e, euW + 128 * 64, eu_b + l * 64, nA, nB, send, rec, e);
        // ---- p message: pA=p@W[0:64), pB=p@W[64:128), e@W[128:192)
        gemm64_kernel<1><<<nodeGrid, 256>>>(
            Src{p, 64, 0, 2}, Z, pmW, zero64, nA, NN);
        gemm64_kernel<1><<<nodeGrid, 256>>>(
            Src{p, 64, 0, 2}, Z, pmW + 64 * 64, zero64, nB, NN);
        init_agg_kernel<<<aggGrid, 256>>>(nB, pm_b + l * 64, deg, pagg);
        streamE_kernel<0><<<edgeGrid, 256, SME_DYN>>>(
            e, pmW + 128 * 64, pm_b + l * 64, nA, nullptr, send, rec, pagg);
        // ---- p update
        gemm64_kernel<2><<<nodeGrid, 256>>>(
            Src{p, 64, 0, 2}, Src{pagg, 64, 0, 2}, puW, pu_b + l * 64, p, NN);
    }

    // Output: (h, p) concatenated
    cudaMemcpyAsync(d_out, h, (size_t)NN * 64 * sizeof(float),
                    cudaMemcpyDeviceToDevice, 0);
    cudaMemcpyAsync((float*)d_out + (size_t)NN * 64, p,
                    (size_t)NN * 64 * sizeof(float),
                    cudaMemcpyDeviceToDevice, 0);
}

// round 7
// speedup vs baseline: 4.6731x; 1.7031x over previous
#include <cuda_runtime.h>
#include <cuda_bf16.h>
#include <cstdint>

#define NN 50000
#define EE 800000

// Scratch state (device globals: allocation-free)
__device__ float g_h[NN * 64];
__device__ float g_p[NN * 64];
__device__ float g_U[NN * 64];
__device__ float g_V[NN * 64];
__device__ float g_A[NN * 64];
__device__ float g_B[NN * 64];
__device__ float g_agg[NN * 64];
__device__ float g_Sagg[NN * 16];
__device__ int   g_deg[NN];
__device__ float g_M[17 * 64];   // rows 0..15: M (16x64), row 16: c
__device__ float g_G[17 * 64];   // rows 0..15: G,        row 16: d
__device__ float g_zero64[64];   // stays zero

struct Chunk {
    const float* X;   // row base (column offset folded into pointer)
    int stride;       // row stride in floats
    const float* W;   // 64x64 weight chunk, row-major
};

// ---------------------------------------------------------------------------
// fp32 node GEMM: out[row](64) = sum_c X_c[row](64) @ W_c + bias
// CTA 256 rows x 64 cols, 256 threads, 8x8 register micro-tile.
template <int NCHUNK>
__global__ void __launch_bounds__(256, 2) gemm64_kernel(
    Chunk c0, Chunk c1, Chunk c2,
    const float* __restrict__ bias, float* __restrict__ out, int nrows)
{
    __shared__ float XsT[32][264];
    __shared__ float Ws[32][72];

    const int tid = threadIdx.x;
    const int row0 = blockIdx.x * 256;
    const int tx = tid & 7;
    const int ty = tid >> 3;

    float acc[8][8];
    {
        float4 b0 = *(const float4*)(bias + tx * 8);
        float4 b1 = *(const float4*)(bias + tx * 8 + 4);
        #pragma unroll
        for (int i = 0; i < 8; i++) {
            acc[i][0] = b0.x; acc[i][1] = b0.y; acc[i][2] = b0.z; acc[i][3] = b0.w;
            acc[i][4] = b1.x; acc[i][5] = b1.y; acc[i][6] = b1.z; acc[i][7] = b1.w;
        }
    }

    const Chunk chunks[3] = {c0, c1, c2};
    const int wr = tid >> 3;
    const int wc = (tid & 7) * 8;

    int myrow = row0 + tid;
    if (myrow > nrows - 1) myrow = nrows - 1;

    #pragma unroll
    for (int c = 0; c < NCHUNK; c++) {
        const float* rp = chunks[c].X + (size_t)myrow * chunks[c].stride;
        const float* wpb = chunks[c].W;

        #pragma unroll
        for (int st = 0; st < 2; st++) {
            __syncthreads();
            #pragma unroll
            for (int i = 0; i < 8; i++) {
                float4 v = *(const float4*)(rp + st * 32 + 4 * i);
                XsT[4 * i + 0][tid] = v.x;
                XsT[4 * i + 1][tid] = v.y;
                XsT[4 * i + 2][tid] = v.z;
                XsT[4 * i + 3][tid] = v.w;
            }
            {
                const float* wp = wpb + (size_t)(st * 32 + wr) * 64 + wc;
                float4 w0 = ((const float4*)wp)[0];
                float4 w1 = ((const float4*)wp)[1];
                float* wd = &Ws[wr][wc];
                ((float4*)wd)[0] = w0;
                ((float4*)wd)[1] = w1;
            }
            __syncthreads();

            #pragma unroll 8
            for (int kk = 0; kk < 32; kk++) {
                float a[8], b[8];
                float4 a0 = *(const float4*)&XsT[kk][ty * 8];
                float4 a1 = *(const float4*)&XsT[kk][ty * 8 + 4];
                float4 bb0 = *(const float4*)&Ws[kk][tx * 8];
                float4 bb1 = *(const float4*)&Ws[kk][tx * 8 + 4];
                a[0] = a0.x; a[1] = a0.y; a[2] = a0.z; a[3] = a0.w;
                a[4] = a1.x; a[5] = a1.y; a[6] = a1.z; a[7] = a1.w;
                b[0] = bb0.x; b[1] = bb0.y; b[2] = bb0.z; b[3] = bb0.w;
                b[4] = bb1.x; b[5] = bb1.y; b[6] = bb1.z; b[7] = bb1.w;
                #pragma unroll
                for (int i = 0; i < 8; i++)
                    #pragma unroll
                    for (int j = 0; j < 8; j++)
                        acc[i][j] += a[i] * b[j];
            }
        }
    }

    #pragma unroll
    for (int i = 0; i < 8; i++) {
        const int grow = row0 + ty * 8 + i;
        if (grow < nrows) {
            float* op = out + (size_t)grow * 64 + tx * 8;
            *(float4*)op = make_float4(acc[i][0], acc[i][1], acc[i][2], acc[i][3]);
            *(float4*)(op + 4) = make_float4(acc[i][4], acc[i][5], acc[i][6], acc[i][7]);
        }
    }
}

// ---------------------------------------------------------------------------
// Weight composition: Mout(17x64) = Min(17x64) @ W3(64x64); row 16 (+bias).
// Single CTA. In-place safe (Min staged in smem).
__global__ void __launch_bounds__(256) compose_kernel(
    const float* __restrict__ Min, const float* __restrict__ W3,
    const float* __restrict__ bias, float* __restrict__ Mout)
{
    __shared__ float Ms[17 * 64];
    const int tid = threadIdx.x;
    for (int i = tid; i < 17 * 64; i += 256) Ms[i] = Min[i];
    __syncthreads();
    for (int i = tid; i < 17 * 64; i += 256) {
        const int r = i >> 6, c = i & 63;
        float acc = (r == 16) ? bias[c] : 0.0f;
        #pragma unroll 8
        for (int k = 0; k < 64; k++) acc += Ms[r * 64 + k] * W3[k * 64 + c];
        Mout[i] = acc;
    }
}

// agg[r][c] = Sagg[r](16) @ G(16x64)[c] + deg[r] * (Bv[r][c] + d[c])
__global__ void __launch_bounds__(256) initagg_kernel(
    const float* __restrict__ Sagg, const float* __restrict__ G,
    const float* __restrict__ Bv, const int* __restrict__ deg,
    float* __restrict__ agg)
{
    __shared__ float Gs[17 * 64];
    const int tid = threadIdx.x;
    for (int i = tid; i < 17 * 64; i += 256) Gs[i] = G[i];
    __syncthreads();
    const int i = blockIdx.x * 256 + tid;
    if (i < NN * 64) {
        const int r = i >> 6, c = i & 63;
        float acc = (float)deg[r] * (Bv[i] + Gs[16 * 64 + c]);
        const float* sp = Sagg + r * 16;
        #pragma unroll
        for (int k = 0; k < 16; k++) acc += sp[k] * Gs[k * 64 + c];
        agg[i] = acc;
    }
}

// agg[rec[j]] += A[send[j]]  (64 wide). 8 threads per edge.
__global__ void __launch_bounds__(256) scatter64_kernel(
    const float* __restrict__ A, const int* __restrict__ send,
    const int* __restrict__ rec, float* __restrict__ agg)
{
    const int tid = threadIdx.x;
    const int e = blockIdx.x * 32 + (tid >> 3);
    const int part = (tid & 7) * 8;
    const int s = send[e];
    const int r = rec[e];
    const float* ap = A + (size_t)s * 64 + part;
    float* op = agg + (size_t)r * 64 + part;
    float4 v0 = *(const float4*)ap;
    float4 v1 = *(const float4*)(ap + 4);
    asm volatile("red.global.add.v4.f32 [%0], {%1, %2, %3, %4};"
                 :: "l"(op), "f"(v0.x), "f"(v0.y), "f"(v0.z), "f"(v0.w) : "memory");
    asm volatile("red.global.add.v4.f32 [%0], {%1, %2, %3, %4};"
                 :: "l"(op + 4), "f"(v1.x), "f"(v1.y), "f"(v1.z), "f"(v1.w) : "memory");
}

// Sagg[rec[j]] += e_in[j]  (16 wide). 4 threads per edge.
__global__ void __launch_bounds__(256) scatter16_kernel(
    const float* __restrict__ e_in, const int* __restrict__ rec,
    float* __restrict__ Sagg)
{
    const int tid = threadIdx.x;
    const int e = blockIdx.x * 64 + (tid >> 2);
    const int part = (tid & 3) * 4;
    const int r = rec[e];
    float4 v = *(const float4*)(e_in + (size_t)e * 16 + part);
    asm volatile("red.global.add.v4.f32 [%0], {%1, %2, %3, %4};"
                 :: "l"(Sagg + (size_t)r * 16 + part),
                    "f"(v.x), "f"(v.y), "f"(v.z), "f"(v.w) : "memory");
}

__global__ void __launch_bounds__(256) deg_kernel(const int* __restrict__ rec,
                                                  int* __restrict__ deg)
{
    int i = blockIdx.x * 256 + threadIdx.x;
    if (i < EE) atomicAdd(&deg[rec[i]], 1);
}

// Small-K embedding (fp32): out[row] = x[row](K) @ W + b
template <int K>
__global__ void __launch_bounds__(256) embed_smallK_kernel(
    const float* __restrict__ x, const float* __restrict__ W,
    const float* __restrict__ bias, float* __restrict__ out, int nrows)
{
    __shared__ float Ws[K][64];
    __shared__ float bsm[64];
    const int tid = threadIdx.x;
    for (int i = tid; i < K * 64; i += 256) Ws[i / 64][i % 64] = W[i];
    if (tid < 64) bsm[tid] = bias[tid];
    __syncthreads();

    const int row = blockIdx.x * 128 + (tid >> 1);
    const int half = (tid & 1) * 32;
    if (row >= nrows) return;

    float xv[K];
    const float4* xp = (const float4*)(x + (size_t)row * K);
    #pragma unroll
    for (int i = 0; i < K / 4; i++) {
        float4 v = xp[i];
        xv[4 * i + 0] = v.x; xv[4 * i + 1] = v.y;
        xv[4 * i + 2] = v.z; xv[4 * i + 3] = v.w;
    }
    float acc[32];
    #pragma unroll
    for (int j = 0; j < 32; j++) acc[j] = bsm[half + j];
    #pragma unroll
    for (int k = 0; k < K; k++) {
        const float xk = xv[k];
        #pragma unroll
        for (int j = 0; j < 32; j++) acc[j] += xk * Ws[k][half + j];
    }
    float* op = out + (size_t)row * 64 + half;
    #pragma unroll
    for (int j = 0; j < 8; j++)
        ((float4*)op)[j] = make_float4(acc[4 * j], acc[4 * j + 1], acc[4 * j + 2], acc[4 * j + 3]);
}

// ---------------------------------------------------------------------------
extern "C" void kernel_launch(void* const* d_in, const int* in_sizes, int n_in,
                              void* d_out, int out_size)
{
    const float* h_in = (const float*)d_in[0];
    const float* e_in = (const float*)d_in[1];
    const float* p_in = (const float*)d_in[2];
    const int* ei = (const int*)d_in[3];
    const float* he_W = (const float*)d_in[4];
    const float* he_b = (const float*)d_in[5];
    const float* ee_W = (const float*)d_in[6];
    const float* ee_b = (const float*)d_in[7];
    const float* pe_W = (const float*)d_in[8];
    const float* pe_b = (const float*)d_in[9];
    const float* hm_W = (const float*)d_in[10];
    const float* hm_b = (const float*)d_in[11];
    const float* hu_W = (const float*)d_in[12];
    const float* hu_b = (const float*)d_in[13];
    const float* eu_W = (const float*)d_in[14];
    const float* eu_b = (const float*)d_in[15];
    const float* pm_W = (const float*)d_in[16];
    const float* pm_b = (const float*)d_in[17];
    const float* pu_W = (const float*)d_in[18];
    const float* pu_b = (const float*)d_in[19];

    const int* send = ei;
    const int* rec = ei + EE;

    float *h, *p, *U, *V, *A, *B, *agg, *Sagg, *M, *G, *zero64;
    int* deg;
    cudaGetSymbolAddress((void**)&h, g_h);
    cudaGetSymbolAddress((void**)&p, g_p);
    cudaGetSymbolAddress((void**)&U, g_U);
    cudaGetSymbolAddress((void**)&V, g_V);
    cudaGetSymbolAddress((void**)&A, g_A);
    cudaGetSymbolAddress((void**)&B, g_B);
    cudaGetSymbolAddress((void**)&agg, g_agg);
    cudaGetSymbolAddress((void**)&Sagg, g_Sagg);
    cudaGetSymbolAddress((void**)&deg, g_deg);
    cudaGetSymbolAddress((void**)&M, g_M);
    cudaGetSymbolAddress((void**)&G, g_G);
    cudaGetSymbolAddress((void**)&zero64, g_zero64);

    const int nodeGrid = (NN + 255) / 256;        // 196
    const int elemGrid = (NN * 64 + 255) / 256;   // 12500

    const Chunk CZ = {nullptr, 0, nullptr};

    // ---- Prologue (all deterministic per call)
    cudaMemsetAsync(U, 0, (size_t)NN * 64 * sizeof(float), 0);
    cudaMemsetAsync(V, 0, (size_t)NN * 64 * sizeof(float), 0);
    cudaMemsetAsync(Sagg, 0, (size_t)NN * 16 * sizeof(float), 0);
    cudaMemsetAsync(deg, 0, NN * sizeof(int), 0);
    scatter16_kernel<<<EE / 64, 256>>>(e_in, rec, Sagg);
    deg_kernel<<<(EE + 255) / 256, 256>>>(rec, deg);

    // Embeddings: h = h_in(128)@he_W + he_b ; p = p_in(16)@pe_W + pe_b
    gemm64_kernel<2><<<nodeGrid, 256>>>(
        Chunk{h_in, 128, he_W}, Chunk{h_in + 64, 128, he_W + 64 * 64}, CZ,
        he_b, h, NN);
    embed_smallK_kernel<16><<<(NN + 127) / 128, 256>>>(p_in, pe_W, pe_b, p, NN);

    // e-state init: M = ee_W (16x64), c = ee_b
    cudaMemcpyAsync(M, ee_W, 16 * 64 * sizeof(float), cudaMemcpyDeviceToDevice, 0);
    cudaMemcpyAsync(M + 16 * 64, ee_b, 64 * sizeof(float), cudaMemcpyDeviceToDevice, 0);

    for (int l = 0; l < 4; l++) {
        const float* hmW = hm_W + (size_t)l * 320 * 64;
        const float* huW = hu_W + (size_t)l * 128 * 64;
        const float* euW = eu_W + (size_t)l * 192 * 64;
        const float* pmW = pm_W + (size_t)l * 192 * 64;
        const float* puW = pu_W + (size_t)l * 128 * 64;
        const float* W3hm = hmW + 256 * 64;
        const float* E3 = euW + 128 * 64;
        const float* P3 = pmW + 128 * 64;

        // G = M@W3hm, d = c@W3hm + hm_b
        compose_kernel<<<1, 256>>>(M, W3hm, hm_b + l * 64, G);
        // A = h@W1 + p@W2 + U@W3hm (send-side) ; Bv = h@W4 + p@W5 + V@W3hm
        gemm64_kernel<3><<<nodeGrid, 256>>>(
            Chunk{h, 64, hmW}, Chunk{p, 64, hmW + 64 * 64}, Chunk{U, 64, W3hm},
            zero64, A, NN);
        gemm64_kernel<3><<<nodeGrid, 256>>>(
            Chunk{h, 64, hmW + 128 * 64}, Chunk{p, 64, hmW + 192 * 64}, Chunk{V, 64, W3hm},
            zero64, B, NN);
        initagg_kernel<<<elemGrid, 256>>>(Sagg, G, B, deg, agg);
        scatter64_kernel<<<EE / 32, 256>>>(A, send, rec, agg);
        // h update
        gemm64_kernel<2><<<nodeGrid, 256>>>(
            Chunk{h, 64, huW}, Chunk{agg, 64, huW + 64 * 64}, CZ,
            hu_b + l * 64, h, NN);
        // e-state recurrence: U=U@E3+h@E1 ; V=V@E3+h@E2 ; M,c=@E3(+eu_b)
        gemm64_kernel<2><<<nodeGrid, 256>>>(
            Chunk{U, 64, E3}, Chunk{h, 64, euW}, CZ, zero64, U, NN);
        gemm64_kernel<2><<<nodeGrid, 256>>>(
            Chunk{V, 64, E3}, Chunk{h, 64, euW + 64 * 64}, CZ, zero64, V, NN);
        compose_kernel<<<1, 256>>>(M, E3, eu_b + l * 64, M);
        // G2 = M@P3, d2 = c@P3 + pm_b
        compose_kernel<<<1, 256>>>(M, P3, pm_b + l * 64, G);
        // A2 = p@P1 + U@P3 ; B2 = p@P2 + V@P3
        gemm64_kernel<2><<<nodeGrid, 256>>>(
            Chunk{p, 64, pmW}, Chunk{U, 64, P3}, CZ, zero64, A, NN);
        gemm64_kernel<2><<<nodeGrid, 256>>>(
            Chunk{p, 64, pmW + 64 * 64}, Chunk{V, 64, P3}, CZ, zero64, B, NN);
        initagg_kernel<<<elemGrid, 256>>>(Sagg, G, B, deg, agg);
        scatter64_kernel<<<EE / 32, 256>>>(A, send, rec, agg);
        // p update
        gemm64_kernel<2><<<nodeGrid, 256>>>(
            Chunk{p, 64, puW}, Chunk{agg, 64, puW + 64 * 64}, CZ,
            pu_b + l * 64, p, NN);
    }

    // Output: (h, p) concatenated
    cudaMemcpyAsync(d_out, h, (size_t)NN * 64 * sizeof(float),
                    cudaMemcpyDeviceToDevice, 0);
    cudaMemcpyAsync((float*)d_out + (size_t)NN * 64, p,
                    (size_t)NN * 64 * sizeof(float),
                    cudaMemcpyDeviceToDevice, 0);
}

// round 9
// speedup vs baseline: 5.4798x; 1.1726x over previous
#include <cuda_runtime.h>
#include <cuda_bf16.h>
#include <cstdint>

#define NN 50000
#define EE 800000

// Scratch state (device globals: allocation-free)
__device__ float g_h[NN * 64];
__device__ float g_p[NN * 64];
__device__ float g_U[NN * 64];
__device__ float g_V[NN * 64];
__device__ float g_A[NN * 64];
__device__ float g_agg[NN * 64];
__device__ float g_Sagg[NN * 16];
__device__ int   g_deg[NN];
__device__ float g_M[17 * 64];    // rows 0..15: M (16x64), row 16: c
__device__ float g_G[17 * 64];    // h-msg composed edge weight
__device__ float g_G2[17 * 64];   // p-msg composed edge weight
__device__ float g_zero64[64];    // stays zero

struct Chunk {
    const float* X;   // row base
    int stride;       // row stride in floats
    const float* W;   // 64x64 weight chunk, row-major
};

struct Job {
    Chunk c0, c1, c2;
    const float* bias;
    float* out;
};

// ---------------------------------------------------------------------------
// Dual-job fp32 node GEMM. blockIdx.y selects job. Each job:
//   out[row](64) = sum_c X_c[row](64) @ W_c + bias
// If EPI_AGG, job 1's epilogue instead writes:
//   out[r][c] = deg[r]*(acc[r][c] + G[16][c]) + Sagg[r](16) @ G[0:16][c]
// CTA 256 rows x 64 cols, 256 threads, 8x8 register micro-tile.
template <int NCHUNK, int EPI_AGG>
__global__ void __launch_bounds__(256, 2) dualgemm_kernel(
    Job j0, Job j1,
    const float* __restrict__ Sagg, const float* __restrict__ Gmat,
    const int* __restrict__ deg, int nrows)
{
    __shared__ float XsT[32][264];
    __shared__ float Ws[32][72];

    const Job& J = (blockIdx.y == 0) ? j0 : j1;
    const bool doEpi = EPI_AGG && (blockIdx.y == 1);

    const int tid = threadIdx.x;
    const int row0 = blockIdx.x * 256;
    const int tx = tid & 7;
    const int ty = tid >> 3;

    float acc[8][8];
    {
        float4 b0 = *(const float4*)(J.bias + tx * 8);
        float4 b1 = *(const float4*)(J.bias + tx * 8 + 4);
        #pragma unroll
        for (int i = 0; i < 8; i++) {
            acc[i][0] = b0.x; acc[i][1] = b0.y; acc[i][2] = b0.z; acc[i][3] = b0.w;
            acc[i][4] = b1.x; acc[i][5] = b1.y; acc[i][6] = b1.z; acc[i][7] = b1.w;
        }
    }

    const Chunk chunks[3] = {J.c0, J.c1, J.c2};
    const int wr = tid >> 3;
    const int wc = (tid & 7) * 8;

    int myrow = row0 + tid;
    if (myrow > nrows - 1) myrow = nrows - 1;

    #pragma unroll
    for (int c = 0; c < NCHUNK; c++) {
        const float* rp = chunks[c].X + (size_t)myrow * chunks[c].stride;
        const float* wpb = chunks[c].W;

        #pragma unroll
        for (int st = 0; st < 2; st++) {
            __syncthreads();
            #pragma unroll
            for (int i = 0; i < 8; i++) {
                float4 v = *(const float4*)(rp + st * 32 + 4 * i);
                XsT[4 * i + 0][tid] = v.x;
                XsT[4 * i + 1][tid] = v.y;
                XsT[4 * i + 2][tid] = v.z;
                XsT[4 * i + 3][tid] = v.w;
            }
            {
                const float* wp = wpb + (size_t)(st * 32 + wr) * 64 + wc;
                float4 w0 = ((const float4*)wp)[0];
                float4 w1 = ((const float4*)wp)[1];
                float* wd = &Ws[wr][wc];
                ((float4*)wd)[0] = w0;
                ((float4*)wd)[1] = w1;
            }
            __syncthreads();

            #pragma unroll 8
            for (int kk = 0; kk < 32; kk++) {
                float a[8], b[8];
                float4 a0 = *(const float4*)&XsT[kk][ty * 8];
                float4 a1 = *(const float4*)&XsT[kk][ty * 8 + 4];
                float4 bb0 = *(const float4*)&Ws[kk][tx * 8];
                float4 bb1 = *(const float4*)&Ws[kk][tx * 8 + 4];
                a[0] = a0.x; a[1] = a0.y; a[2] = a0.z; a[3] = a0.w;
                a[4] = a1.x; a[5] = a1.y; a[6] = a1.z; a[7] = a1.w;
                b[0] = bb0.x; b[1] = bb0.y; b[2] = bb0.z; b[3] = bb0.w;
                b[4] = bb1.x; b[5] = bb1.y; b[6] = bb1.z; b[7] = bb1.w;
                #pragma unroll
                for (int i = 0; i < 8; i++)
                    #pragma unroll
                    for (int j = 0; j < 8; j++)
                        acc[i][j] += a[i] * b[j];
            }
        }
    }

    if (doEpi) {
        // Stage G (17x64) into smem (reuse Ws+XsT region via flat view of XsT)
        float* Gs = &XsT[0][0];
        __syncthreads();
        for (int i = tid; i < 17 * 64; i += 256) Gs[i] = Gmat[i];
        __syncthreads();
        #pragma unroll
        for (int i = 0; i < 8; i++) {
            const int grow = row0 + ty * 8 + i;
            if (grow < nrows) {
                const float dg = (float)deg[grow];
                float sg[16];
                const float4* sp = (const float4*)(Sagg + (size_t)grow * 16);
                #pragma unroll
                for (int q = 0; q < 4; q++) {
                    float4 v = sp[q];
                    sg[4 * q] = v.x; sg[4 * q + 1] = v.y;
                    sg[4 * q + 2] = v.z; sg[4 * q + 3] = v.w;
                }
                float res[8];
                #pragma unroll
                for (int j = 0; j < 8; j++) {
                    const int col = tx * 8 + j;
                    float v = dg * (acc[i][j] + Gs[16 * 64 + col]);
                    #pragma unroll
                    for (int k = 0; k < 16; k++) v += sg[k] * Gs[k * 64 + col];
                    res[j] = v;
                }
                float* op = J.out + (size_t)grow * 64 + tx * 8;
                *(float4*)op = make_float4(res[0], res[1], res[2], res[3]);
                *(float4*)(op + 4) = make_float4(res[4], res[5], res[6], res[7]);
            }
        }
    } else {
        #pragma unroll
        for (int i = 0; i < 8; i++) {
            const int grow = row0 + ty * 8 + i;
            if (grow < nrows) {
                float* op = J.out + (size_t)grow * 64 + tx * 8;
                *(float4*)op = make_float4(acc[i][0], acc[i][1], acc[i][2], acc[i][3]);
                *(float4*)(op + 4) = make_float4(acc[i][4], acc[i][5], acc[i][6], acc[i][7]);
            }
        }
    }
}

// ---------------------------------------------------------------------------
// Per-layer weight composition (single CTA):
//   G  = M @ W3hm   (row16: c@W3hm + hm_b)
//   Mn = M @ E3     (row16: c@E3 + eu_b)    -> written back to M
//   G2 = Mn @ P3    (row16: cn@P3 + pm_b)
__global__ void __launch_bounds__(256) composeAll_kernel(
    float* __restrict__ M,
    const float* __restrict__ W3hm, const float* __restrict__ E3,
    const float* __restrict__ P3,
    const float* __restrict__ hm_b, const float* __restrict__ eu_b,
    const float* __restrict__ pm_b,
    float* __restrict__ G, float* __restrict__ G2)
{
    __shared__ float Ms[17 * 64];
    __shared__ float Mn[17 * 64];
    const int tid = threadIdx.x;
    for (int i = tid; i < 17 * 64; i += 256) Ms[i] = M[i];
    __syncthreads();
    for (int i = tid; i < 17 * 64; i += 256) {
        const int r = i >> 6, c = i & 63;
        float accG = (r == 16) ? hm_b[c] : 0.0f;
        float accM = (r == 16) ? eu_b[c] : 0.0f;
        #pragma unroll 8
        for (int k = 0; k < 64; k++) {
            const float m = Ms[r * 64 + k];
            accG += m * W3hm[k * 64 + c];
            accM += m * E3[k * 64 + c];
        }
        G[i] = accG;
        Mn[i] = accM;
        M[i] = accM;
    }
    __syncthreads();
    for (int i = tid; i < 17 * 64; i += 256) {
        const int r = i >> 6, c = i & 63;
        float acc = (r == 16) ? pm_b[c] : 0.0f;
        #pragma unroll 8
        for (int k = 0; k < 64; k++) acc += Mn[r * 64 + k] * P3[k * 64 + c];
        G2[i] = acc;
    }
}

// agg[rec[j]] += A[send[j]]  (64 wide). 8 threads per edge.
__global__ void __launch_bounds__(256) scatter64_kernel(
    const float* __restrict__ A, const int* __restrict__ send,
    const int* __restrict__ rec, float* __restrict__ agg)
{
    const int tid = threadIdx.x;
    const int e = blockIdx.x * 32 + (tid >> 3);
    const int part = (tid & 7) * 8;
    const int s = send[e];
    const int r = rec[e];
    const float* ap = A + (size_t)s * 64 + part;
    float* op = agg + (size_t)r * 64 + part;
    float4 v0 = *(const float4*)ap;
    float4 v1 = *(const float4*)(ap + 4);
    asm volatile("red.global.add.v4.f32 [%0], {%1, %2, %3, %4};"
                 :: "l"(op), "f"(v0.x), "f"(v0.y), "f"(v0.z), "f"(v0.w) : "memory");
    asm volatile("red.global.add.v4.f32 [%0], {%1, %2, %3, %4};"
                 :: "l"(op + 4), "f"(v1.x), "f"(v1.y), "f"(v1.z), "f"(v1.w) : "memory");
}

// Sagg[rec[j]] += e_in[j]  (16 wide). 4 threads per edge.
__global__ void __launch_bounds__(256) scatter16_kernel(
    const float* __restrict__ e_in, const int* __restrict__ rec,
    float* __restrict__ Sagg)
{
    const int tid = threadIdx.x;
    const int e = blockIdx.x * 64 + (tid >> 2);
    const int part = (tid & 3) * 4;
    const int r = rec[e];
    float4 v = *(const float4*)(e_in + (size_t)e * 16 + part);
    asm volatile("red.global.add.v4.f32 [%0], {%1, %2, %3, %4};"
                 :: "l"(Sagg + (size_t)r * 16 + part),
                    "f"(v.x), "f"(v.y), "f"(v.z), "f"(v.w) : "memory");
}

__global__ void __launch_bounds__(256) deg_kernel(const int* __restrict__ rec,
                                                  int* __restrict__ deg)
{
    int i = blockIdx.x * 256 + threadIdx.x;
    if (i < EE) atomicAdd(&deg[rec[i]], 1);
}

// Small-K embedding (fp32): out[row] = x[row](K) @ W + b
template <int K>
__global__ void __launch_bounds__(256) embed_smallK_kernel(
    const float* __restrict__ x, const float* __restrict__ W,
    const float* __restrict__ bias, float* __restrict__ out, int nrows)
{
    __shared__ float Ws[K][64];
    __shared__ float bsm[64];
    const int tid = threadIdx.x;
    for (int i = tid; i < K * 64; i += 256) Ws[i / 64][i % 64] = W[i];
    if (tid < 64) bsm[tid] = bias[tid];
    __syncthreads();

    const int row = blockIdx.x * 128 + (tid >> 1);
    const int half = (tid & 1) * 32;
    if (row >= nrows) return;

    float xv[K];
    const float4* xp = (const float4*)(x + (size_t)row * K);
    #pragma unroll
    for (int i = 0; i < K / 4; i++) {
        float4 v = xp[i];
        xv[4 * i + 0] = v.x; xv[4 * i + 1] = v.y;
        xv[4 * i + 2] = v.z; xv[4 * i + 3] = v.w;
    }
    float acc[32];
    #pragma unroll
    for (int j = 0; j < 32; j++) acc[j] = bsm[half + j];
    #pragma unroll
    for (int k = 0; k < K; k++) {
        const float xk = xv[k];
        #pragma unroll
        for (int j = 0; j < 32; j++) acc[j] += xk * Ws[k][half + j];
    }
    float* op = out + (size_t)row * 64 + half;
    #pragma unroll
    for (int j = 0; j < 8; j++)
        ((float4*)op)[j] = make_float4(acc[4 * j], acc[4 * j + 1], acc[4 * j + 2], acc[4 * j + 3]);
}

// ---------------------------------------------------------------------------
extern "C" void kernel_launch(void* const* d_in, const int* in_sizes, int n_in,
                              void* d_out, int out_size)
{
    const float* h_in = (const float*)d_in[0];
    const float* e_in = (const float*)d_in[1];
    const float* p_in = (const float*)d_in[2];
    const int* ei = (const int*)d_in[3];
    const float* he_W = (const float*)d_in[4];
    const float* he_b = (const float*)d_in[5];
    const float* ee_W = (const float*)d_in[6];
    const float* ee_b = (const float*)d_in[7];
    const float* pe_W = (const float*)d_in[8];
    const float* pe_b = (const float*)d_in[9];
    const float* hm_W = (const float*)d_in[10];
    const float* hm_b = (const float*)d_in[11];
    const float* hu_W = (const float*)d_in[12];
    const float* hu_b = (const float*)d_in[13];
    const float* eu_W = (const float*)d_in[14];
    const float* eu_b = (const float*)d_in[15];
    const float* pm_W = (const float*)d_in[16];
    const float* pm_b = (const float*)d_in[17];
    const float* pu_W = (const float*)d_in[18];
    const float* pu_b = (const float*)d_in[19];

    const int* send = ei;
    const int* rec = ei + EE;

    float *h, *p, *U, *V, *A, *agg, *Sagg, *M, *G, *G2, *zero64;
    int* deg;
    cudaGetSymbolAddress((void**)&h, g_h);
    cudaGetSymbolAddress((void**)&p, g_p);
    cudaGetSymbolAddress((void**)&U, g_U);
    cudaGetSymbolAddress((void**)&V, g_V);
    cudaGetSymbolAddress((void**)&A, g_A);
    cudaGetSymbolAddress((void**)&agg, g_agg);
    cudaGetSymbolAddress((void**)&Sagg, g_Sagg);
    cudaGetSymbolAddress((void**)&deg, g_deg);
    cudaGetSymbolAddress((void**)&M, g_M);
    cudaGetSymbolAddress((void**)&G, g_G);
    cudaGetSymbolAddress((void**)&G2, g_G2);
    cudaGetSymbolAddress((void**)&zero64, g_zero64);

    const int nodeGrid = (NN + 255) / 256;  // 196
    const dim3 dualGrid(nodeGrid, 2);

    const Chunk CZ = {nullptr, 0, nullptr};

    // ---- Prologue
    cudaMemsetAsync(U, 0, (size_t)NN * 64 * sizeof(float), 0);
    cudaMemsetAsync(V, 0, (size_t)NN * 64 * sizeof(float), 0);
    cudaMemsetAsync(Sagg, 0, (size_t)NN * 16 * sizeof(float), 0);
    cudaMemsetAsync(deg, 0, NN * sizeof(int), 0);
    scatter16_kernel<<<EE / 64, 256>>>(e_in, rec, Sagg);
    deg_kernel<<<(EE + 255) / 256, 256>>>(rec, deg);

    // Embeddings (dual: h-embed split into 2 K=64 chunks; p-embed separate)
    dualgemm_kernel<2, 0><<<dim3(nodeGrid, 1), 256>>>(
        Job{Chunk{h_in, 128, he_W}, Chunk{h_in + 64, 128, he_W + 64 * 64}, CZ, he_b, h},
        Job{}, nullptr, nullptr, nullptr, NN);
    embed_smallK_kernel<16><<<(NN + 127) / 128, 256>>>(p_in, pe_W, pe_b, p, NN);

    // e-state init: M = ee_W (16x64), c = ee_b
    cudaMemcpyAsync(M, ee_W, 16 * 64 * sizeof(float), cudaMemcpyDeviceToDevice, 0);
    cudaMemcpyAsync(M + 16 * 64, ee_b, 64 * sizeof(float), cudaMemcpyDeviceToDevice, 0);

    for (int l = 0; l < 4; l++) {
        const float* hmW = hm_W + (size_t)l * 320 * 64;
        const float* huW = hu_W + (size_t)l * 128 * 64;
        const float* euW = eu_W + (size_t)l * 192 * 64;
        const float* pmW = pm_W + (size_t)l * 192 * 64;
        const float* puW = pu_W + (size_t)l * 128 * 64;
        const float* W3hm = hmW + 256 * 64;
        const float* E3 = euW + 128 * 64;
        const float* P3 = pmW + 128 * 64;

        // 1. Compose G (h-msg), M update (e-update), G2 (p-msg)
        composeAll_kernel<<<1, 256>>>(M, W3hm, E3, P3,
                                      hm_b + l * 64, eu_b + l * 64, pm_b + l * 64,
                                      G, G2);
        // 2. A = h@W1 + p@W2 + U@W3hm ;  agg = deg*(h@W4+p@W5+V@W3hm + d) + Sagg@G
        dualgemm_kernel<3, 1><<<dualGrid, 256>>>(
            Job{Chunk{h, 64, hmW}, Chunk{p, 64, hmW + 64 * 64}, Chunk{U, 64, W3hm}, zero64, A},
            Job{Chunk{h, 64, hmW + 128 * 64}, Chunk{p, 64, hmW + 192 * 64}, Chunk{V, 64, W3hm}, zero64, agg},
            Sagg, G, deg, NN);
        // 3. agg += A[send]
        scatter64_kernel<<<EE / 32, 256>>>(A, send, rec, agg);
        // 4. h update
        dualgemm_kernel<2, 0><<<dim3(nodeGrid, 1), 256>>>(
            Job{Chunk{h, 64, huW}, Chunk{agg, 64, huW + 64 * 64}, CZ, hu_b + l * 64, h},
            Job{}, nullptr, nullptr, nullptr, NN);
        // 5. U = U@E3 + h@E1 ; V = V@E3 + h@E2
        dualgemm_kernel<2, 0><<<dualGrid, 256>>>(
            Job{Chunk{U, 64, E3}, Chunk{h, 64, euW}, CZ, zero64, U},
            Job{Chunk{V, 64, E3}, Chunk{h, 64, euW + 64 * 64}, CZ, zero64, V},
            nullptr, nullptr, nullptr, NN);
        // 6. A = p@P1 + U@P3 ;  agg = deg*(p@P2+V@P3 + d2) + Sagg@G2
        dualgemm_kernel<2, 1><<<dualGrid, 256>>>(
            Job{Chunk{p, 64, pmW}, Chunk{U, 64, P3}, CZ, zero64, A},
            Job{Chunk{p, 64, pmW + 64 * 64}, Chunk{V, 64, P3}, CZ, zero64, agg},
            Sagg, G2, deg, NN);
        // 7. agg += A[send]
        scatter64_kernel<<<EE / 32, 256>>>(A, send, rec, agg);
        // 8. p update
        dualgemm_kernel<2, 0><<<dim3(nodeGrid, 1), 256>>>(
            Job{Chunk{p, 64, puW}, Chunk{agg, 64, puW + 64 * 64}, CZ, pu_b + l * 64, p},
            Job{}, nullptr, nullptr, nullptr, NN);
    }

    // Output: (h, p) concatenated
    cudaMemcpyAsync(d_out, h, (size_t)NN * 64 * sizeof(float),
                    cudaMemcpyDeviceToDevice, 0);
    cudaMemcpyAsync((float*)d_out + (size_t)NN * 64, p,
                    (size_t)NN * 64 * sizeof(float),
                    cudaMemcpyDeviceToDevice, 0);
}

// round 11
// speedup vs baseline: 6.9067x; 1.2604x over previous
#include <cuda_runtime.h>
#include <cuda_bf16.h>
#include <cstdint>

#define NN 50000
#define EE 800000

// Scratch state (device globals: allocation-free)
__device__ float g_h[NN * 64];
__device__ float g_p[NN * 64];
__device__ float g_U[NN * 64];
__device__ float g_V[NN * 64];
__device__ float g_A[NN * 64];
__device__ float g_agg[NN * 64];
__device__ float g_Sagg[NN * 16];
__device__ int   g_deg[NN];
__device__ float g_M[17 * 64];    // rows 0..15: M (16x64), row 16: c
__device__ float g_G[17 * 64];    // h-msg composed edge weight
__device__ float g_G2[17 * 64];   // p-msg composed edge weight
__device__ float g_zero64[64];    // stays zero

struct Chunk {
    const float* X;   // row base
    int stride;       // row stride in floats
    const float* W;   // 64x64 weight chunk, row-major
};

struct Job {
    Chunk c0, c1, c2;
    const float* bias;
    float* out;
};

__device__ __forceinline__ void split_tf32(float x, float& hi, float& lo) {
    uint32_t hb;
    asm("cvt.rna.tf32.f32 %0, %1;" : "=r"(hb) : "f"(x));
    hi = __uint_as_float(hb);
    float l = x - hi;
    uint32_t lb;
    asm("cvt.rna.tf32.f32 %0, %1;" : "=r"(lb) : "f"(l));
    lo = __uint_as_float(lb);
}

#define MMA(d, a0, a1, a2, a3, b0, b1)                                        \
    asm volatile(                                                             \
        "mma.sync.aligned.m16n8k8.row.col.f32.tf32.tf32.f32 "                 \
        "{%0,%1,%2,%3}, {%4,%5,%6,%7}, {%8,%9}, {%0,%1,%2,%3};"               \
        : "+f"(d[0]), "+f"(d[1]), "+f"(d[2]), "+f"(d[3])                      \
        : "r"(a0), "r"(a1), "r"(a2), "r"(a3), "r"(b0), "r"(b1))

// ---------------------------------------------------------------------------
// Dual-job node GEMM, 3xTF32 (fp32-accurate). blockIdx.y selects job:
//   out[row](64) = sum_c X_c[row](64) @ W_c + bias
// If EPI_AGG, job 1's epilogue instead writes:
//   out[r][c] = deg[r]*(acc[r][c] + G[16][c]) + Sagg[r](16) @ G[0:16][c]
// CTA 256 rows x 64 cols, 8 warps; warp tile 32 rows x 64 cols (m16n8k8).
template <int NCHUNK, int EPI_AGG>
__global__ void __launch_bounds__(256, 2) dualgemm_kernel(
    Job j0, Job j1,
    const float* __restrict__ Sagg, const float* __restrict__ Gmat,
    const int* __restrict__ deg, int nrows)
{
    extern __shared__ float dyn[];
    float* Xhi = dyn;                  // [256][36]
    float* Xlo = Xhi + 256 * 36;
    float* Whi = Xlo + 256 * 36;       // [32][72]
    float* Wlo = Whi + 32 * 72;
    __shared__ float bs[64];

    const Job& J = (blockIdx.y == 0) ? j0 : j1;
    const bool doEpi = EPI_AGG && (blockIdx.y == 1);

    const int tid = threadIdx.x;
    const int row0 = blockIdx.x * 256;
    const int lane = tid & 31;
    const int warp = tid >> 5;
    const int warpRow0 = warp * 32;
    const int qrow = lane >> 2;   // 0..7
    const int qk = lane & 3;      // 0..3

    if (tid < 64) bs[tid] = J.bias[tid];

    float acc[2][8][4];
    #pragma unroll
    for (int mt = 0; mt < 2; mt++)
        #pragma unroll
        for (int nt = 0; nt < 8; nt++)
            #pragma unroll
            for (int r = 0; r < 4; r++) acc[mt][nt][r] = 0.0f;

    const Chunk chunks[3] = {J.c0, J.c1, J.c2};
    const int wr = tid >> 3;
    const int wc = (tid & 7) * 8;

    #pragma unroll
    for (int c = 0; c < NCHUNK; c++) {
        const float* Xb = chunks[c].X;
        const int stride = chunks[c].stride;
        const float* wpb = chunks[c].W;

        #pragma unroll
        for (int st = 0; st < 2; st++) {
            __syncthreads();
            // X slab: coalesced, 4 floats per thread per iter
            #pragma unroll
            for (int i = 0; i < 8; i++) {
                const int g = tid + 256 * i;
                const int row = g >> 3;
                const int f = (g & 7) * 4;
                int grow = row0 + row;
                if (grow > nrows - 1) grow = nrows - 1;
                float4 v = *(const float4*)(Xb + (size_t)grow * stride + st * 32 + f);
                float hi[4], lo[4];
                split_tf32(v.x, hi[0], lo[0]);
                split_tf32(v.y, hi[1], lo[1]);
                split_tf32(v.z, hi[2], lo[2]);
                split_tf32(v.w, hi[3], lo[3]);
                *(float4*)&Xhi[row * 36 + f] = make_float4(hi[0], hi[1], hi[2], hi[3]);
                *(float4*)&Xlo[row * 36 + f] = make_float4(lo[0], lo[1], lo[2], lo[3]);
            }
            // W slab
            {
                const float* wp = wpb + (size_t)(st * 32 + wr) * 64 + wc;
                #pragma unroll
                for (int j = 0; j < 8; j++) {
                    float hi, lo;
                    split_tf32(wp[j], hi, lo);
                    Whi[wr * 72 + wc + j] = hi;
                    Wlo[wr * 72 + wc + j] = lo;
                }
            }
            __syncthreads();

            #pragma unroll
            for (int ks = 0; ks < 4; ks++) {
                const int k0 = ks * 8;
                uint32_t ah[2][4], al[2][4];
                #pragma unroll
                for (int mt = 0; mt < 2; mt++) {
                    const int r = warpRow0 + mt * 16 + qrow;
                    ah[mt][0] = __float_as_uint(Xhi[r * 36 + k0 + qk]);
                    ah[mt][1] = __float_as_uint(Xhi[(r + 8) * 36 + k0 + qk]);
                    ah[mt][2] = __float_as_uint(Xhi[r * 36 + k0 + qk + 4]);
                    ah[mt][3] = __float_as_uint(Xhi[(r + 8) * 36 + k0 + qk + 4]);
                    al[mt][0] = __float_as_uint(Xlo[r * 36 + k0 + qk]);
                    al[mt][1] = __float_as_uint(Xlo[(r + 8) * 36 + k0 + qk]);
                    al[mt][2] = __float_as_uint(Xlo[r * 36 + k0 + qk + 4]);
                    al[mt][3] = __float_as_uint(Xlo[(r + 8) * 36 + k0 + qk + 4]);
                }
                #pragma unroll
                for (int nt = 0; nt < 8; nt++) {
                    const int cb = nt * 8 + qrow;
                    uint32_t bh0 = __float_as_uint(Whi[(k0 + qk) * 72 + cb]);
                    uint32_t bh1 = __float_as_uint(Whi[(k0 + qk + 4) * 72 + cb]);
                    uint32_t bl0 = __float_as_uint(Wlo[(k0 + qk) * 72 + cb]);
                    uint32_t bl1 = __float_as_uint(Wlo[(k0 + qk + 4) * 72 + cb]);
                    #pragma unroll
                    for (int mt = 0; mt < 2; mt++) {
                        MMA(acc[mt][nt], ah[mt][0], ah[mt][1], ah[mt][2], ah[mt][3], bh0, bh1);
                        MMA(acc[mt][nt], ah[mt][0], ah[mt][1], ah[mt][2], ah[mt][3], bl0, bl1);
                        MMA(acc[mt][nt], al[mt][0], al[mt][1], al[mt][2], al[mt][3], bh0, bh1);
                    }
                }
            }
        }
    }

    if (doEpi) {
        // Stage G (17x64) in smem (reuse Xhi)
        __syncthreads();
        for (int i = tid; i < 17 * 64; i += 256) Xhi[i] = Gmat[i];
        __syncthreads();
        #pragma unroll
        for (int mt = 0; mt < 2; mt++) {
            #pragma unroll
            for (int half = 0; half < 2; half++) {
                const int r = warpRow0 + mt * 16 + qrow + half * 8;
                const int grow = row0 + r;
                if (grow < nrows) {
                    const float dg = (float)deg[grow];
                    float sg[16];
                    const float4* sp = (const float4*)(Sagg + (size_t)grow * 16);
                    #pragma unroll
                    for (int q = 0; q < 4; q++) {
                        float4 v = sp[q];
                        sg[4 * q] = v.x; sg[4 * q + 1] = v.y;
                        sg[4 * q + 2] = v.z; sg[4 * q + 3] = v.w;
                    }
                    #pragma unroll
                    for (int nt = 0; nt < 8; nt++) {
                        const int col = nt * 8 + 2 * qk;
                        float v0 = dg * (acc[mt][nt][half * 2 + 0] + Xhi[16 * 64 + col]);
                        float v1 = dg * (acc[mt][nt][half * 2 + 1] + Xhi[16 * 64 + col + 1]);
                        #pragma unroll
                        for (int k = 0; k < 16; k++) {
                            v0 += sg[k] * Xhi[k * 64 + col];
                            v1 += sg[k] * Xhi[k * 64 + col + 1];
                        }
                        *(float2*)(J.out + (size_t)grow * 64 + col) = make_float2(v0, v1);
                    }
                }
            }
        }
    } else {
        #pragma unroll
        for (int mt = 0; mt < 2; mt++) {
            #pragma unroll
            for (int half = 0; half < 2; half++) {
                const int r = warpRow0 + mt * 16 + qrow + half * 8;
                const int grow = row0 + r;
                if (grow < nrows) {
                    #pragma unroll
                    for (int nt = 0; nt < 8; nt++) {
                        const int col = nt * 8 + 2 * qk;
                        float v0 = acc[mt][nt][half * 2 + 0] + bs[col];
                        float v1 = acc[mt][nt][half * 2 + 1] + bs[col + 1];
                        *(float2*)(J.out + (size_t)grow * 64 + col) = make_float2(v0, v1);
                    }
                }
            }
        }
    }
}

// ---------------------------------------------------------------------------
// Per-layer weight composition (single CTA):
//   G  = M @ W3hm (+hm_b) ; M <- M @ E3 (+eu_b) ; G2 = Mnew @ P3 (+pm_b)
__global__ void __launch_bounds__(256) composeAll_kernel(
    float* __restrict__ M,
    const float* __restrict__ W3hm, const float* __restrict__ E3,
    const float* __restrict__ P3,
    const float* __restrict__ hm_b, const float* __restrict__ eu_b,
    const float* __restrict__ pm_b,
    float* __restrict__ G, float* __restrict__ G2)
{
    __shared__ float Ms[17 * 64];
    __shared__ float Mn[17 * 64];
    const int tid = threadIdx.x;
    for (int i = tid; i < 17 * 64; i += 256) Ms[i] = M[i];
    __syncthreads();
    for (int i = tid; i < 17 * 64; i += 256) {
        const int r = i >> 6, c = i & 63;
        float accG = (r == 16) ? hm_b[c] : 0.0f;
        float accM = (r == 16) ? eu_b[c] : 0.0f;
        #pragma unroll 8
        for (int k = 0; k < 64; k++) {
            const float m = Ms[r * 64 + k];
            accG += m * W3hm[k * 64 + c];
            accM += m * E3[k * 64 + c];
        }
        G[i] = accG;
        Mn[i] = accM;
        M[i] = accM;
    }
    __syncthreads();
    for (int i = tid; i < 17 * 64; i += 256) {
        const int r = i >> 6, c = i & 63;
        float acc = (r == 16) ? pm_b[c] : 0.0f;
        #pragma unroll 8
        for (int k = 0; k < 64; k++) acc += Mn[r * 64 + k] * P3[k * 64 + c];
        G2[i] = acc;
    }
}

// agg[rec[j]] += A[send[j]]  (64 wide). 8 threads per edge.
__global__ void __launch_bounds__(256) scatter64_kernel(
    const float* __restrict__ A, const int* __restrict__ send,
    const int* __restrict__ rec, float* __restrict__ agg)
{
    const int tid = threadIdx.x;
    const int e = blockIdx.x * 32 + (tid >> 3);
    const int part = (tid & 7) * 8;
    const int s = send[e];
    const int r = rec[e];
    const float* ap = A + (size_t)s * 64 + part;
    float* op = agg + (size_t)r * 64 + part;
    float4 v0 = *(const float4*)ap;
    float4 v1 = *(const float4*)(ap + 4);
    asm volatile("red.global.add.v4.f32 [%0], {%1, %2, %3, %4};"
                 :: "l"(op), "f"(v0.x), "f"(v0.y), "f"(v0.z), "f"(v0.w) : "memory");
    asm volatile("red.global.add.v4.f32 [%0], {%1, %2, %3, %4};"
                 :: "l"(op + 4), "f"(v1.x), "f"(v1.y), "f"(v1.z), "f"(v1.w) : "memory");
}

// Sagg[rec[j]] += e_in[j]  (16 wide). 4 threads per edge.
__global__ void __launch_bounds__(256) scatter16_kernel(
    const float* __restrict__ e_in, const int* __restrict__ rec,
    float* __restrict__ Sagg)
{
    const int tid = threadIdx.x;
    const int e = blockIdx.x * 64 + (tid >> 2);
    const int part = (tid & 3) * 4;
    const int r = rec[e];
    float4 v = *(const float4*)(e_in + (size_t)e * 16 + part);
    asm volatile("red.global.add.v4.f32 [%0], {%1, %2, %3, %4};"
                 :: "l"(Sagg + (size_t)r * 16 + part),
                    "f"(v.x), "f"(v.y), "f"(v.z), "f"(v.w) : "memory");
}

__global__ void __launch_bounds__(256) deg_kernel(const int* __restrict__ rec,
                                                  int* __restrict__ deg)
{
    int i = blockIdx.x * 256 + threadIdx.x;
    if (i < EE) atomicAdd(&deg[rec[i]], 1);
}

// Small-K embedding (fp32): out[row] = x[row](K) @ W + b
template <int K>
__global__ void __launch_bounds__(256) embed_smallK_kernel(
    const float* __restrict__ x, const float* __restrict__ W,
    const float* __restrict__ bias, float* __restrict__ out, int nrows)
{
    __shared__ float Ws[K][64];
    __shared__ float bsm[64];
    const int tid = threadIdx.x;
    for (int i = tid; i < K * 64; i += 256) Ws[i / 64][i % 64] = W[i];
    if (tid < 64) bsm[tid] = bias[tid];
    __syncthreads();

    const int row = blockIdx.x * 128 + (tid >> 1);
    const int half = (tid & 1) * 32;
    if (row >= nrows) return;

    float xv[K];
    const float4* xp = (const float4*)(x + (size_t)row * K);
    #pragma unroll
    for (int i = 0; i < K / 4; i++) {
        float4 v = xp[i];
        xv[4 * i + 0] = v.x; xv[4 * i + 1] = v.y;
        xv[4 * i + 2] = v.z; xv[4 * i + 3] = v.w;
    }
    float acc[32];
    #pragma unroll
    for (int j = 0; j < 32; j++) acc[j] = bsm[half + j];
    #pragma unroll
    for (int k = 0; k < K; k++) {
        const float xk = xv[k];
        #pragma unroll
        for (int j = 0; j < 32; j++) acc[j] += xk * Ws[k][half + j];
    }
    float* op = out + (size_t)row * 64 + half;
    #pragma unroll
    for (int j = 0; j < 8; j++)
        ((float4*)op)[j] = make_float4(acc[4 * j], acc[4 * j + 1], acc[4 * j + 2], acc[4 * j + 3]);
}

// ---------------------------------------------------------------------------
extern "C" void kernel_launch(void* const* d_in, const int* in_sizes, int n_in,
                              void* d_out, int out_size)
{
    const float* h_in = (const float*)d_in[0];
    const float* e_in = (const float*)d_in[1];
    const float* p_in = (const float*)d_in[2];
    const int* ei = (const int*)d_in[3];
    const float* he_W = (const float*)d_in[4];
    const float* he_b = (const float*)d_in[5];
    const float* ee_W = (const float*)d_in[6];
    const float* ee_b = (const float*)d_in[7];
    const float* pe_W = (const float*)d_in[8];
    const float* pe_b = (const float*)d_in[9];
    const float* hm_W = (const float*)d_in[10];
    const float* hm_b = (const float*)d_in[11];
    const float* hu_W = (const float*)d_in[12];
    const float* hu_b = (const float*)d_in[13];
    const float* eu_W = (const float*)d_in[14];
    const float* eu_b = (const float*)d_in[15];
    const float* pm_W = (const float*)d_in[16];
    const float* pm_b = (const float*)d_in[17];
    const float* pu_W = (const float*)d_in[18];
    const float* pu_b = (const float*)d_in[19];

    const int* send = ei;
    const int* rec = ei + EE;

    float *h, *p, *U, *V, *A, *agg, *Sagg, *M, *G, *G2, *zero64;
    int* deg;
    cudaGetSymbolAddress((void**)&h, g_h);
    cudaGetSymbolAddress((void**)&p, g_p);
    cudaGetSymbolAddress((void**)&U, g_U);
    cudaGetSymbolAddress((void**)&V, g_V);
    cudaGetSymbolAddress((void**)&A, g_A);
    cudaGetSymbolAddress((void**)&agg, g_agg);
    cudaGetSymbolAddress((void**)&Sagg, g_Sagg);
    cudaGetSymbolAddress((void**)&deg, g_deg);
    cudaGetSymbolAddress((void**)&M, g_M);
    cudaGetSymbolAddress((void**)&G, g_G);
    cudaGetSymbolAddress((void**)&G2, g_G2);
    cudaGetSymbolAddress((void**)&zero64, g_zero64);

    const int SME = (256 * 36 * 2 + 32 * 72 * 2) * 4;  // 92160 B
    cudaFuncSetAttribute(dualgemm_kernel<2, 0>, cudaFuncAttributeMaxDynamicSharedMemorySize, SME);
    cudaFuncSetAttribute(dualgemm_kernel<2, 1>, cudaFuncAttributeMaxDynamicSharedMemorySize, SME);
    cudaFuncSetAttribute(dualgemm_kernel<3, 1>, cudaFuncAttributeMaxDynamicSharedMemorySize, SME);

    const int nodeGrid = (NN + 255) / 256;  // 196
    const dim3 dualGrid(nodeGrid, 2);

    const Chunk CZ = {nullptr, 0, nullptr};

    // ---- Prologue
    cudaMemsetAsync(U, 0, (size_t)NN * 64 * sizeof(float), 0);
    cudaMemsetAsync(V, 0, (size_t)NN * 64 * sizeof(float), 0);
    cudaMemsetAsync(Sagg, 0, (size_t)NN * 16 * sizeof(float), 0);
    cudaMemsetAsync(deg, 0, NN * sizeof(int), 0);
    scatter16_kernel<<<EE / 64, 256>>>(e_in, rec, Sagg);
    deg_kernel<<<(EE + 255) / 256, 256>>>(rec, deg);

    // Embeddings: h = h_in(128)@he_W + he_b (tf32 dual kernel); p (fp32)
    dualgemm_kernel<2, 0><<<dim3(nodeGrid, 1), 256, SME>>>(
        Job{Chunk{h_in, 128, he_W}, Chunk{h_in + 64, 128, he_W + 64 * 64}, CZ, he_b, h},
        Job{}, nullptr, nullptr, nullptr, NN);
    embed_smallK_kernel<16><<<(NN + 127) / 128, 256>>>(p_in, pe_W, pe_b, p, NN);

    // e-state init: M = ee_W (16x64), c = ee_b
    cudaMemcpyAsync(M, ee_W, 16 * 64 * sizeof(float), cudaMemcpyDeviceToDevice, 0);
    cudaMemcpyAsync(M + 16 * 64, ee_b, 64 * sizeof(float), cudaMemcpyDeviceToDevice, 0);

    for (int l = 0; l < 4; l++) {
        const float* hmW = hm_W + (size_t)l * 320 * 64;
        const float* huW = hu_W + (size_t)l * 128 * 64;
        const float* euW = eu_W + (size_t)l * 192 * 64;
        const float* pmW = pm_W + (size_t)l * 192 * 64;
        const float* puW = pu_W + (size_t)l * 128 * 64;
        const float* W3hm = hmW + 256 * 64;
        const float* E3 = euW + 128 * 64;
        const float* P3 = pmW + 128 * 64;

        // 1. Compose G (h-msg), M update (e-update), G2 (p-msg)
        composeAll_kernel<<<1, 256>>>(M, W3hm, E3, P3,
                                      hm_b + l * 64, eu_b + l * 64, pm_b + l * 64,
                                      G, G2);
        // 2. A = h@W1 + p@W2 + U@W3hm ;  agg = deg*(h@W4+p@W5+V@W3hm + d) + Sagg@G
        dualgemm_kernel<3, 1><<<dualGrid, 256, SME>>>(
            Job{Chunk{h, 64, hmW}, Chunk{p, 64, hmW + 64 * 64}, Chunk{U, 64, W3hm}, zero64, A},
            Job{Chunk{h, 64, hmW + 128 * 64}, Chunk{p, 64, hmW + 192 * 64}, Chunk{V, 64, W3hm}, zero64, agg},
            Sagg, G, deg, NN);
        // 3. agg += A[send]
        scatter64_kernel<<<EE / 32, 256>>>(A, send, rec, agg);
        // 4. h update
        dualgemm_kernel<2, 0><<<dim3(nodeGrid, 1), 256, SME>>>(
            Job{Chunk{h, 64, huW}, Chunk{agg, 64, huW + 64 * 64}, CZ, hu_b + l * 64, h},
            Job{}, nullptr, nullptr, nullptr, NN);
        // 5. U = U@E3 + h@E1 ; V = V@E3 + h@E2
        dualgemm_kernel<2, 0><<<dualGrid, 256, SME>>>(
            Job{Chunk{U, 64, E3}, Chunk{h, 64, euW}, CZ, zero64, U},
            Job{Chunk{V, 64, E3}, Chunk{h, 64, euW + 64 * 64}, CZ, zero64, V},
            nullptr, nullptr, nullptr, NN);
        // 6. A = p@P1 + U@P3 ;  agg = deg*(p@P2+V@P3 + d2) + Sagg@G2
        dualgemm_kernel<2, 1><<<dualGrid, 256, SME>>>(
            Job{Chunk{p, 64, pmW}, Chunk{U, 64, P3}, CZ, zero64, A},
            Job{Chunk{p, 64, pmW + 64 * 64}, Chunk{V, 64, P3}, CZ, zero64, agg},
            Sagg, G2, deg, NN);
        // 7. agg += A[send]
        scatter64_kernel<<<EE / 32, 256>>>(A, send, rec, agg);
        // 8. p update
        dualgemm_kernel<2, 0><<<dim3(nodeGrid, 1), 256, SME>>>(
            Job{Chunk{p, 64, puW}, Chunk{agg, 64, puW + 64 * 64}, CZ, pu_b + l * 64, p},
            Job{}, nullptr, nullptr, nullptr, NN);
    }

    // Output: (h, p) concatenated
    cudaMemcpyAsync(d_out, h, (size_t)NN * 64 * sizeof(float),
                    cudaMemcpyDeviceToDevice, 0);
    cudaMemcpyAsync((float*)d_out + (size_t)NN * 64, p,
                    (size_t)NN * 64 * sizeof(float),
                    cudaMemcpyDeviceToDevice, 0);
}

// round 13
// speedup vs baseline: 8.6548x; 1.2531x over previous
#include <cuda_runtime.h>
#include <cuda_bf16.h>
#include <cstdint>

#define NN 50000
#define EE 800000

// Scratch state (device globals: allocation-free)
__device__ float g_h[NN * 64];
__device__ float g_p[NN * 64];
__device__ float g_U[NN * 64];
__device__ float g_V[NN * 64];
__device__ float g_A[NN * 64];
__device__ float g_agg[NN * 64];
__device__ float g_Sagg[NN * 16];
__device__ int   g_deg[NN];
__device__ float g_M[17 * 64];    // rows 0..15: M (16x64), row 16: c
__device__ float g_G[17 * 64];    // h-msg composed edge weight
__device__ float g_G2[17 * 64];   // p-msg composed edge weight
__device__ float g_zero64[64];    // stays zero

struct Chunk {
    const float* X;   // row base
    int stride;       // row stride in floats
    const float* W;   // 64x64 weight chunk, row-major
};

struct Job {
    Chunk c0, c1, c2;
    const float* bias;
    float* out;
};

__device__ __forceinline__ void split_bf16(float x, __nv_bfloat16& hi, __nv_bfloat16& lo) {
    hi = __float2bfloat16_rn(x);
    lo = __float2bfloat16_rn(x - __bfloat162float(hi));
}

#define MMAB(d, a0, a1, a2, a3, b0, b1)                                       \
    asm volatile(                                                             \
        "mma.sync.aligned.m16n8k16.row.col.f32.bf16.bf16.f32 "                \
        "{%0,%1,%2,%3}, {%4,%5,%6,%7}, {%8,%9}, {%0,%1,%2,%3};"               \
        : "+f"(d[0]), "+f"(d[1]), "+f"(d[2]), "+f"(d[3])                      \
        : "r"(a0), "r"(a1), "r"(a2), "r"(a3), "r"(b0), "r"(b1))

// ---------------------------------------------------------------------------
// Dual-job node GEMM, 3xBF16 (near-fp32): blockIdx.y selects job.
//   out[row](64) = sum_c X_c[row](64) @ W_c + bias
// If EPI_AGG, job 1's epilogue instead writes:
//   out[r][c] = deg[r]*(acc[r][c] + G[16][c]) + Sagg[r](16) @ G[0:16][c]
// CTA 256 rows x 64 cols, 8 warps; warp tile 32 rows x 64 cols (m16n8k16).
template <int NCHUNK, int EPI_AGG>
__global__ void __launch_bounds__(256, 2) dualgemm_kernel(
    Job j0, Job j1,
    const float* __restrict__ Sagg, const float* __restrict__ Gmat,
    const int* __restrict__ deg, int nrows)
{
    extern __shared__ char dynraw[];
    __nv_bfloat16* Xhi = (__nv_bfloat16*)dynraw;     // [256][72] (K=64 + pad)
    __nv_bfloat16* Xlo = Xhi + 256 * 72;
    __nv_bfloat16* Whi = Xlo + 256 * 72;             // [col][k]: [64][72]
    __nv_bfloat16* Wlo = Whi + 64 * 72;
    __shared__ float bs[64];

    const Job& J = (blockIdx.y == 0) ? j0 : j1;
    const bool doEpi = EPI_AGG && (blockIdx.y == 1);

    const int tid = threadIdx.x;
    const int row0 = blockIdx.x * 256;
    const int lane = tid & 31;
    const int warp = tid >> 5;
    const int warpRow0 = warp * 32;
    const int qrow = lane >> 2;   // 0..7
    const int qk = lane & 3;      // 0..3

    if (tid < 64) bs[tid] = J.bias[tid];

    float acc[2][8][4];
    #pragma unroll
    for (int mt = 0; mt < 2; mt++)
        #pragma unroll
        for (int nt = 0; nt < 8; nt++)
            #pragma unroll
            for (int r = 0; r < 4; r++) acc[mt][nt][r] = 0.0f;

    const Chunk chunks[3] = {J.c0, J.c1, J.c2};

    // W loader mapping: coalesced (lane = col), 16 k's per thread
    const int wcol = tid & 63;
    const int wkb = (tid >> 6) * 16;

    #pragma unroll
    for (int c = 0; c < NCHUNK; c++) {
        const float* Xb = chunks[c].X;
        const int stride = chunks[c].stride;
        const float* wpb = chunks[c].W;

        __syncthreads();
        // X: 256 rows x 64 floats; 16 float4 per row, coalesced
        #pragma unroll
        for (int i = 0; i < 16; i++) {
            const int g = tid + 256 * i;
            const int row = g >> 4;
            const int f = (g & 15) * 4;
            int grow = row0 + row;
            if (grow > nrows - 1) grow = nrows - 1;
            float4 v = *(const float4*)(Xb + (size_t)grow * stride + f);
            __nv_bfloat16 h0, l0, h1, l1, h2, l2, h3, l3;
            split_bf16(v.x, h0, l0);
            split_bf16(v.y, h1, l1);
            split_bf16(v.z, h2, l2);
            split_bf16(v.w, h3, l3);
            __nv_bfloat162* ph = (__nv_bfloat162*)(Xhi + row * 72 + f);
            __nv_bfloat162* pl = (__nv_bfloat162*)(Xlo + row * 72 + f);
            ph[0] = __nv_bfloat162{h0, h1};
            ph[1] = __nv_bfloat162{h2, h3};
            pl[0] = __nv_bfloat162{l0, l1};
            pl[1] = __nv_bfloat162{l2, l3};
        }
        // W: store transposed [col][k] so the k16 B-fragment is packed
        #pragma unroll
        for (int j = 0; j < 16; j += 2) {
            float x0 = wpb[(size_t)(wkb + j) * 64 + wcol];
            float x1 = wpb[(size_t)(wkb + j + 1) * 64 + wcol];
            __nv_bfloat16 h0, l0, h1, l1;
            split_bf16(x0, h0, l0);
            split_bf16(x1, h1, l1);
            *(__nv_bfloat162*)(Whi + wcol * 72 + wkb + j) = __nv_bfloat162{h0, h1};
            *(__nv_bfloat162*)(Wlo + wcol * 72 + wkb + j) = __nv_bfloat162{l0, l1};
        }
        __syncthreads();

        #pragma unroll
        for (int ks = 0; ks < 4; ks++) {
            const int k0 = ks * 16;
            uint32_t ah[2][4], al[2][4];
            #pragma unroll
            for (int mt = 0; mt < 2; mt++) {
                const int r = warpRow0 + mt * 16 + qrow;
                ah[mt][0] = *(const uint32_t*)(Xhi + r * 72 + k0 + 2 * qk);
                ah[mt][1] = *(const uint32_t*)(Xhi + (r + 8) * 72 + k0 + 2 * qk);
                ah[mt][2] = *(const uint32_t*)(Xhi + r * 72 + k0 + 2 * qk + 8);
                ah[mt][3] = *(const uint32_t*)(Xhi + (r + 8) * 72 + k0 + 2 * qk + 8);
                al[mt][0] = *(const uint32_t*)(Xlo + r * 72 + k0 + 2 * qk);
                al[mt][1] = *(const uint32_t*)(Xlo + (r + 8) * 72 + k0 + 2 * qk);
                al[mt][2] = *(const uint32_t*)(Xlo + r * 72 + k0 + 2 * qk + 8);
                al[mt][3] = *(const uint32_t*)(Xlo + (r + 8) * 72 + k0 + 2 * qk + 8);
            }
            #pragma unroll
            for (int nt = 0; nt < 8; nt++) {
                const int col = nt * 8 + qrow;
                uint32_t bh0 = *(const uint32_t*)(Whi + col * 72 + k0 + 2 * qk);
                uint32_t bh1 = *(const uint32_t*)(Whi + col * 72 + k0 + 2 * qk + 8);
                uint32_t bl0 = *(const uint32_t*)(Wlo + col * 72 + k0 + 2 * qk);
                uint32_t bl1 = *(const uint32_t*)(Wlo + col * 72 + k0 + 2 * qk + 8);
                #pragma unroll
                for (int mt = 0; mt < 2; mt++) {
                    MMAB(acc[mt][nt], ah[mt][0], ah[mt][1], ah[mt][2], ah[mt][3], bh0, bh1);
                    MMAB(acc[mt][nt], ah[mt][0], ah[mt][1], ah[mt][2], ah[mt][3], bl0, bl1);
                    MMAB(acc[mt][nt], al[mt][0], al[mt][1], al[mt][2], al[mt][3], bh0, bh1);
                }
            }
        }
    }

    if (doEpi) {
        // Stage G (17x64 floats) in smem (reuse Xhi region)
        float* Gs = (float*)Xhi;
        __syncthreads();
        for (int i = tid; i < 17 * 64; i += 256) Gs[i] = Gmat[i];
        __syncthreads();
        #pragma unroll
        for (int mt = 0; mt < 2; mt++) {
            #pragma unroll
            for (int half = 0; half < 2; half++) {
                const int r = warpRow0 + mt * 16 + qrow + half * 8;
                const int grow = row0 + r;
                if (grow < nrows) {
                    const float dg = (float)deg[grow];
                    float sg[16];
                    const float4* sp = (const float4*)(Sagg + (size_t)grow * 16);
                    #pragma unroll
                    for (int q = 0; q < 4; q++) {
                        float4 v = sp[q];
                        sg[4 * q] = v.x; sg[4 * q + 1] = v.y;
                        sg[4 * q + 2] = v.z; sg[4 * q + 3] = v.w;
                    }
                    #pragma unroll
                    for (int nt = 0; nt < 8; nt++) {
                        const int col = nt * 8 + 2 * qk;
                        float v0 = dg * (acc[mt][nt][half * 2 + 0] + Gs[16 * 64 + col]);
                        float v1 = dg * (acc[mt][nt][half * 2 + 1] + Gs[16 * 64 + col + 1]);
                        #pragma unroll
                        for (int k = 0; k < 16; k++) {
                            v0 += sg[k] * Gs[k * 64 + col];
                            v1 += sg[k] * Gs[k * 64 + col + 1];
                        }
                        *(float2*)(J.out + (size_t)grow * 64 + col) = make_float2(v0, v1);
                    }
                }
            }
        }
    } else {
        #pragma unroll
        for (int mt = 0; mt < 2; mt++) {
            #pragma unroll
            for (int half = 0; half < 2; half++) {
                const int r = warpRow0 + mt * 16 + qrow + half * 8;
                const int grow = row0 + r;
                if (grow < nrows) {
                    #pragma unroll
                    for (int nt = 0; nt < 8; nt++) {
                        const int col = nt * 8 + 2 * qk;
                        float v0 = acc[mt][nt][half * 2 + 0] + bs[col];
                        float v1 = acc[mt][nt][half * 2 + 1] + bs[col + 1];
                        *(float2*)(J.out + (size_t)grow * 64 + col) = make_float2(v0, v1);
                    }
                }
            }
        }
    }
}

// ---------------------------------------------------------------------------
// Per-layer weight composition (single CTA, fp32):
//   G  = M @ W3hm (+hm_b) ; M <- M @ E3 (+eu_b) ; G2 = Mnew @ P3 (+pm_b)
__global__ void __launch_bounds__(256) composeAll_kernel(
    float* __restrict__ M,
    const float* __restrict__ W3hm, const float* __restrict__ E3,
    const float* __restrict__ P3,
    const float* __restrict__ hm_b, const float* __restrict__ eu_b,
    const float* __restrict__ pm_b,
    float* __restrict__ G, float* __restrict__ G2)
{
    __shared__ float Ms[17 * 64];
    __shared__ float Mn[17 * 64];
    const int tid = threadIdx.x;
    for (int i = tid; i < 17 * 64; i += 256) Ms[i] = M[i];
    __syncthreads();
    for (int i = tid; i < 17 * 64; i += 256) {
        const int r = i >> 6, c = i & 63;
        float accG = (r == 16) ? hm_b[c] : 0.0f;
        float accM = (r == 16) ? eu_b[c] : 0.0f;
        #pragma unroll 8
        for (int k = 0; k < 64; k++) {
            const float m = Ms[r * 64 + k];
            accG += m * W3hm[k * 64 + c];
            accM += m * E3[k * 64 + c];
        }
        G[i] = accG;
        Mn[i] = accM;
        M[i] = accM;
    }
    __syncthreads();
    for (int i = tid; i < 17 * 64; i += 256) {
        const int r = i >> 6, c = i & 63;
        float acc = (r == 16) ? pm_b[c] : 0.0f;
        #pragma unroll 8
        for (int k = 0; k < 64; k++) acc += Mn[r * 64 + k] * P3[k * 64 + c];
        G2[i] = acc;
    }
}

// agg[rec[j]] += A[send[j]]  (64 wide). 8 threads per edge.
__global__ void __launch_bounds__(256) scatter64_kernel(
    const float* __restrict__ A, const int* __restrict__ send,
    const int* __restrict__ rec, float* __restrict__ agg)
{
    const int tid = threadIdx.x;
    const int e = blockIdx.x * 32 + (tid >> 3);
    const int part = (tid & 7) * 8;
    const int s = send[e];
    const int r = rec[e];
    const float* ap = A + (size_t)s * 64 + part;
    float* op = agg + (size_t)r * 64 + part;
    float4 v0 = *(const float4*)ap;
    float4 v1 = *(const float4*)(ap + 4);
    asm volatile("red.global.add.v4.f32 [%0], {%1, %2, %3, %4};"
                 :: "l"(op), "f"(v0.x), "f"(v0.y), "f"(v0.z), "f"(v0.w) : "memory");
    asm volatile("red.global.add.v4.f32 [%0], {%1, %2, %3, %4};"
                 :: "l"(op + 4), "f"(v1.x), "f"(v1.y), "f"(v1.z), "f"(v1.w) : "memory");
}

// Sagg[rec[j]] += e_in[j]  (16 wide). 4 threads per edge.
__global__ void __launch_bounds__(256) scatter16_kernel(
    const float* __restrict__ e_in, const int* __restrict__ rec,
    float* __restrict__ Sagg)
{
    const int tid = threadIdx.x;
    const int e = blockIdx.x * 64 + (tid >> 2);
    const int part = (tid & 3) * 4;
    const int r = rec[e];
    float4 v = *(const float4*)(e_in + (size_t)e * 16 + part);
    asm volatile("red.global.add.v4.f32 [%0], {%1, %2, %3, %4};"
                 :: "l"(Sagg + (size_t)r * 16 + part),
                    "f"(v.x), "f"(v.y), "f"(v.z), "f"(v.w) : "memory");
}

__global__ void __launch_bounds__(256) deg_kernel(const int* __restrict__ rec,
                                                  int* __restrict__ deg)
{
    int i = blockIdx.x * 256 + threadIdx.x;
    if (i < EE) atomicAdd(&deg[rec[i]], 1);
}

// Small-K embedding (fp32): out[row] = x[row](K) @ W + b
template <int K>
__global__ void __launch_bounds__(256) embed_smallK_kernel(
    const float* __restrict__ x, const float* __restrict__ W,
    const float* __restrict__ bias, float* __restrict__ out, int nrows)
{
    __shared__ float Ws[K][64];
    __shared__ float bsm[64];
    const int tid = threadIdx.x;
    for (int i = tid; i < K * 64; i += 256) Ws[i / 64][i % 64] = W[i];
    if (tid < 64) bsm[tid] = bias[tid];
    __syncthreads();

    const int row = blockIdx.x * 128 + (tid >> 1);
    const int half = (tid & 1) * 32;
    if (row >= nrows) return;

    float xv[K];
    const float4* xp = (const float4*)(x + (size_t)row * K);
    #pragma unroll
    for (int i = 0; i < K / 4; i++) {
        float4 v = xp[i];
        xv[4 * i + 0] = v.x; xv[4 * i + 1] = v.y;
        xv[4 * i + 2] = v.z; xv[4 * i + 3] = v.w;
    }
    float acc[32];
    #pragma unroll
    for (int j = 0; j < 32; j++) acc[j] = bsm[half + j];
    #pragma unroll
    for (int k = 0; k < K; k++) {
        const float xk = xv[k];
        #pragma unroll
        for (int j = 0; j < 32; j++) acc[j] += xk * Ws[k][half + j];
    }
    float* op = out + (size_t)row * 64 + half;
    #pragma unroll
    for (int j = 0; j < 8; j++)
        ((float4*)op)[j] = make_float4(acc[4 * j], acc[4 * j + 1], acc[4 * j + 2], acc[4 * j + 3]);
}

// ---------------------------------------------------------------------------
extern "C" void kernel_launch(void* const* d_in, const int* in_sizes, int n_in,
                              void* d_out, int out_size)
{
    const float* h_in = (const float*)d_in[0];
    const float* e_in = (const float*)d_in[1];
    const float* p_in = (const float*)d_in[2];
    const int* ei = (const int*)d_in[3];
    const float* he_W = (const float*)d_in[4];
    const float* he_b = (const float*)d_in[5];
    const float* ee_W = (const float*)d_in[6];
    const float* ee_b = (const float*)d_in[7];
    const float* pe_W = (const float*)d_in[8];
    const float* pe_b = (const float*)d_in[9];
    const float* hm_W = (const float*)d_in[10];
    const float* hm_b = (const float*)d_in[11];
    const float* hu_W = (const float*)d_in[12];
    const float* hu_b = (const float*)d_in[13];
    const float* eu_W = (const float*)d_in[14];
    const float* eu_b = (const float*)d_in[15];
    const float* pm_W = (const float*)d_in[16];
    const float* pm_b = (const float*)d_in[17];
    const float* pu_W = (const float*)d_in[18];
    const float* pu_b = (const float*)d_in[19];

    const int* send = ei;
    const int* rec = ei + EE;

    float *h, *p, *U, *V, *A, *agg, *Sagg, *M, *G, *G2, *zero64;
    int* deg;
    cudaGetSymbolAddress((void**)&h, g_h);
    cudaGetSymbolAddress((void**)&p, g_p);
    cudaGetSymbolAddress((void**)&U, g_U);
    cudaGetSymbolAddress((void**)&V, g_V);
    cudaGetSymbolAddress((void**)&A, g_A);
    cudaGetSymbolAddress((void**)&agg, g_agg);
    cudaGetSymbolAddress((void**)&Sagg, g_Sagg);
    cudaGetSymbolAddress((void**)&deg, g_deg);
    cudaGetSymbolAddress((void**)&M, g_M);
    cudaGetSymbolAddress((void**)&G, g_G);
    cudaGetSymbolAddress((void**)&G2, g_G2);
    cudaGetSymbolAddress((void**)&zero64, g_zero64);

    // bf16 hi/lo: X 2*[256][72] + W 2*[64][72], 2 bytes each
    const int SME = (256 * 72 * 2 + 64 * 72 * 2) * 2;  // 92160 B
    cudaFuncSetAttribute(dualgemm_kernel<2, 0>, cudaFuncAttributeMaxDynamicSharedMemorySize, SME);
    cudaFuncSetAttribute(dualgemm_kernel<2, 1>, cudaFuncAttributeMaxDynamicSharedMemorySize, SME);
    cudaFuncSetAttribute(dualgemm_kernel<3, 1>, cudaFuncAttributeMaxDynamicSharedMemorySize, SME);

    const int nodeGrid = (NN + 255) / 256;  // 196
    const dim3 dualGrid(nodeGrid, 2);

    const Chunk CZ = {nullptr, 0, nullptr};

    // ---- Prologue
    cudaMemsetAsync(U, 0, (size_t)NN * 64 * sizeof(float), 0);
    cudaMemsetAsync(V, 0, (size_t)NN * 64 * sizeof(float), 0);
    cudaMemsetAsync(Sagg, 0, (size_t)NN * 16 * sizeof(float), 0);
    cudaMemsetAsync(deg, 0, NN * sizeof(int), 0);
    scatter16_kernel<<<EE / 64, 256>>>(e_in, rec, Sagg);
    deg_kernel<<<(EE + 255) / 256, 256>>>(rec, deg);

    // Embeddings: h = h_in(128)@he_W + he_b (bf16-3x dual kernel); p (fp32)
    dualgemm_kernel<2, 0><<<dim3(nodeGrid, 1), 256, SME>>>(
        Job{Chunk{h_in, 128, he_W}, Chunk{h_in + 64, 128, he_W + 64 * 64}, CZ, he_b, h},
        Job{}, nullptr, nullptr, nullptr, NN);
    embed_smallK_kernel<16><<<(NN + 127) / 128, 256>>>(p_in, pe_W, pe_b, p, NN);

    // e-state init: M = ee_W (16x64), c = ee_b
    cudaMemcpyAsync(M, ee_W, 16 * 64 * sizeof(float), cudaMemcpyDeviceToDevice, 0);
    cudaMemcpyAsync(M + 16 * 64, ee_b, 64 * sizeof(float), cudaMemcpyDeviceToDevice, 0);

    for (int l = 0; l < 4; l++) {
        const float* hmW = hm_W + (size_t)l * 320 * 64;
        const float* huW = hu_W + (size_t)l * 128 * 64;
        const float* euW = eu_W + (size_t)l * 192 * 64;
        const float* pmW = pm_W + (size_t)l * 192 * 64;
        const float* puW = pu_W + (size_t)l * 128 * 64;
        const float* W3hm = hmW + 256 * 64;
        const float* E3 = euW + 128 * 64;
        const float* P3 = pmW + 128 * 64;

        // 1. Compose G (h-msg), M update (e-update), G2 (p-msg)
        composeAll_kernel<<<1, 256>>>(M, W3hm, E3, P3,
                                      hm_b + l * 64, eu_b + l * 64, pm_b + l * 64,
                                      G, G2);
        // 2. A = h@W1 + p@W2 + U@W3hm ;  agg = deg*(h@W4+p@W5+V@W3hm + d) + Sagg@G
        dualgemm_kernel<3, 1><<<dualGrid, 256, SME>>>(
            Job{Chunk{h, 64, hmW}, Chunk{p, 64, hmW + 64 * 64}, Chunk{U, 64, W3hm}, zero64, A},
            Job{Chunk{h, 64, hmW + 128 * 64}, Chunk{p, 64, hmW + 192 * 64}, Chunk{V, 64, W3hm}, zero64, agg},
            Sagg, G, deg, NN);
        // 3. agg += A[send]
        scatter64_kernel<<<EE / 32, 256>>>(A, send, rec, agg);
        // 4. h update
        dualgemm_kernel<2, 0><<<dim3(nodeGrid, 1), 256, SME>>>(
            Job{Chunk{h, 64, huW}, Chunk{agg, 64, huW + 64 * 64}, CZ, hu_b + l * 64, h},
            Job{}, nullptr, nullptr, nullptr, NN);
        // 5. U = U@E3 + h@E1 ; V = V@E3 + h@E2
        dualgemm_kernel<2, 0><<<dualGrid, 256, SME>>>(
            Job{Chunk{U, 64, E3}, Chunk{h, 64, euW}, CZ, zero64, U},
            Job{Chunk{V, 64, E3}, Chunk{h, 64, euW + 64 * 64}, CZ, zero64, V},
            nullptr, nullptr, nullptr, NN);
        // 6. A = p@P1 + U@P3 ;  agg = deg*(p@P2+V@P3 + d2) + Sagg@G2
        dualgemm_kernel<2, 1><<<dualGrid, 256, SME>>>(
            Job{Chunk{p, 64, pmW}, Chunk{U, 64, P3}, CZ, zero64, A},
            Job{Chunk{p, 64, pmW + 64 * 64}, Chunk{V, 64, P3}, CZ, zero64, agg},
            Sagg, G2, deg, NN);
        // 7. agg += A[send]
        scatter64_kernel<<<EE / 32, 256>>>(A, send, rec, agg);
        // 8. p update
        dualgemm_kernel<2, 0><<<dim3(nodeGrid, 1), 256, SME>>>(
            Job{Chunk{p, 64, puW}, Chunk{agg, 64, puW + 64 * 64}, CZ, pu_b + l * 64, p},
            Job{}, nullptr, nullptr, nullptr, NN);
    }

    // Output: (h, p) concatenated
    cudaMemcpyAsync(d_out, h, (size_t)NN * 64 * sizeof(float),
                    cudaMemcpyDeviceToDevice, 0);
    cudaMemcpyAsync((float*)d_out + (size_t)NN * 64, p,
                    (size_t)NN * 64 * sizeof(float),
                    cudaMemcpyDeviceToDevice, 0);
}